// round 10
// baseline (speedup 1.0000x reference)
#include <cuda_runtime.h>
#include <math.h>

#define B_ 32
#define T_ 32
#define F_ 64
#define H_ 256
#define N_ 1024
#define A_ 64
#define C_ 192
#define M_ 256
#define HSOFF (T_*H_*B_)

// ---------------- precomputed globals ----------------
__device__ __align__(16) float g_addrT[A_*N_];     // addrT[a*1024+n]
__device__ __align__(16) float g_giA[T_*B_*768];   // gi: [(t*32+b)*768+row]
__device__ __align__(16) float g_cxA[T_*B_*C_];    // Wci@x: [(t*32+b)*192+c]

__device__ __forceinline__ float warp_sum(float v) {
    #pragma unroll
    for (int o = 16; o; o >>= 1) v += __shfl_xor_sync(0xffffffffu, v, o);
    return v;
}
__device__ __forceinline__ float warp_max(float v) {
    #pragma unroll
    for (int o = 16; o; o >>= 1) v = fmaxf(v, __shfl_xor_sync(0xffffffffu, v, o));
    return v;
}

__device__ __forceinline__ float dot8(float4 w1, float4 w2, float4 h1, float4 h2) {
    return w1.x*h1.x + w1.y*h1.y + w1.z*h1.z + w1.w*h1.w
         + w2.x*h2.x + w2.y*h2.y + w2.z*h2.z + w2.w*h2.w;
}

// warp-cooperative log-softmax head for (tstep, b); reads s_h
__device__ __forceinline__ void head_out(const float* __restrict__ Wout,
                                         const float* __restrict__ bo,
                                         const float* __restrict__ s_h,
                                         float* __restrict__ out,
                                         int tstep, int b, int lane) {
    float logit[10];
    float mx = -1e30f;
    #pragma unroll
    for (int o = 0; o < 10; o++) {
        float s = 0.f;
        #pragma unroll
        for (int j = 0; j < 8; j++) {
            int k = lane + 32*j;
            s += Wout[o*H_ + k] * s_h[k];
        }
        s = warp_sum(s);
        s += bo[o];
        logit[o] = s;
        mx = fmaxf(mx, s);
    }
    float se = 0.f;
    #pragma unroll
    for (int o = 0; o < 10; o++) se += expf(logit[o] - mx);
    float lse = mx + logf(se);
    if (lane == 0) {
        #pragma unroll
        for (int o = 0; o < 10; o++)
            out[HSOFF + (tstep*10 + o)*B_ + b] = logit[o] - lse;
    }
}

// ================= K0: init (once) =================
__global__ __launch_bounds__(256, 4)
void k_init(const float* __restrict__ batch, const float* __restrict__ addr,
            const float* __restrict__ Wi, const float* __restrict__ bi,
            const float* __restrict__ Wci)
{
    int blk = blockIdx.x, tid = threadIdx.x, lane = tid & 31, wl = tid >> 5;
    if (blk < 1024) {
        int t = blk >> 5, b = blk & 31;
        __shared__ float sx[64];
        if (tid < 64) {
            int idx = tid*32 + b;          // raw-reshape: x_t[f,b] = flat[f*32+b]
            sx[tid] = batch[(idx >> 6)*(T_*F_) + t*F_ + (idx & 63)];
        }
        __syncthreads();
        for (int r = wl; r < 960; r += 8) {
            if (r < 768) {
                float acc = Wi[r*64 + lane]*sx[lane] + Wi[r*64 + 32 + lane]*sx[32 + lane];
                acc = warp_sum(acc);
                if (lane == 0) g_giA[(t*32 + b)*768 + r] = acc + bi[r];
            } else {
                int c = r - 768;
                float acc = Wci[c*64 + lane]*sx[lane] + Wci[c*64 + 32 + lane]*sx[32 + lane];
                acc = warp_sum(acc);
                if (lane == 0) g_cxA[(t*32 + b)*192 + c] = acc;
            }
        }
    } else {
        for (int i = (blk - 1024)*256 + tid; i < A_*N_; i += 8*256) {
            int a = i >> 10, n = i & 1023;
            g_addrT[i] = addr[n*A_ + a];
        }
    }
}

// ================= K1: whole recurrence, one block per b =================
// smem layout (floats):
//  [0      .. 32768)  whist[32][1024]
//  [32768  .. 38912)  cand[32][192]
//  [38912  .. 39680)  gi[768]
//  [39680  .. 40448)  gh[768]
//  [40448  .. 40704)  q[256]
//  [40704  .. 40960)  h[256]
//  [40960  .. 41216)  r[256]
//  [41216  .. 41248)  d[32]
//  [41248  .. 41280)  G[32]
//  [41280  .. 41312)  m[32]
//  [41312  .. 41344)  e[32]
//  [41344]            beta
#define SMEM_FLOATS 41360
__global__ __launch_bounds__(1024, 1)
void k_run(const float* __restrict__ Wh,  const float* __restrict__ bh,
           const float* __restrict__ Wq,  const float* __restrict__ bq,
           const float* __restrict__ Wch, const float* __restrict__ uvec,
           const float* __restrict__ Wm,  const float* __restrict__ bm,
           const float* __restrict__ Wout,const float* __restrict__ bo,
           float* __restrict__ out)
{
    extern __shared__ __align__(16) float sm[];
    float* s_w    = sm;
    float* s_cand = sm + 32768;
    float* s_gi   = sm + 38912;
    float* s_gh   = sm + 39680;
    float* s_q    = sm + 40448;
    float* s_h    = sm + 40704;
    float* s_r    = sm + 40960;
    float* s_d    = sm + 41216;
    float* s_G    = sm + 41248;
    float* s_m    = sm + 41280;
    float* s_e    = sm + 41312;
    float* s_beta = sm + 41344;

    const int b = blockIdx.x;
    const int tid = threadIdx.x, lane = tid & 31, wl = tid >> 5;
    const float4* h4 = (const float4*)s_h;
    const float4* r4 = (const float4*)s_r;

    if (tid < 256) s_h[tid] = 0.f;
    __syncthreads();

    for (int t = 0; t < T_; t++) {
        // ---- stage 1: gh, q, cand, beta (row-per-warp) + gi load + head(t-1) ----
        if (tid < 768) s_gi[tid] = g_giA[(t*32 + b)*768 + tid];
        for (int r = wl; r < 1218; r += 32) {
            if (r < 768) {
                const float4* w4 = (const float4*)Wh + r*64;
                float acc = dot8(w4[lane], w4[32 + lane], h4[lane], h4[32 + lane]);
                acc = warp_sum(acc);
                if (lane == 0) s_gh[r] = acc + bh[r];
            } else if (r < 1024) {
                int m = r - 768;
                const float4* w4 = (const float4*)Wq + m*64;
                float acc = dot8(w4[lane], w4[32 + lane], h4[lane], h4[32 + lane]);
                acc = warp_sum(acc);
                if (lane == 0) s_q[m] = acc + bq[m];
            } else if (r < 1216) {
                int c = r - 1024;
                const float4* w4 = (const float4*)Wch + c*64;
                float acc = dot8(w4[lane], w4[32 + lane], h4[lane], h4[32 + lane]);
                acc = warp_sum(acc);
                if (lane == 0)
                    s_cand[t*192 + c] = fmaxf(acc + g_cxA[(t*32 + b)*192 + c], 0.f);
            } else if (r == 1216) {
                const float4* u4 = (const float4*)uvec;
                float acc = dot8(u4[lane], u4[32 + lane], h4[lane], h4[32 + lane]);
                acc = warp_sum(acc);
                if (lane == 0) {
                    float sp = (acc > 0.f) ? acc + log1pf(expf(-acc)) : log1pf(expf(acc));
                    s_beta[0] = sp + 1.f;
                }
            } else {
                if (t > 0) head_out(Wout, bo, s_h, out, t - 1, b, lane);
            }
        }
        __syncthreads();

        // ---- stage 2: d_s = cand_s . q_c (warp per s < t) ----
        if (wl < t) {
            float acc = 0.f;
            #pragma unroll
            for (int j = 0; j < 6; j++) {
                int c = lane + 32*j;
                acc += s_cand[wl*192 + c] * s_q[A_ + c];
            }
            acc = warp_sum(acc);
            if (lane == 0) s_d[wl] = acc;
        }
        __syncthreads();

        // ---- stage 3: sim (thread-per-n) + block softmax -> w ----
        {
            int n = tid;
            float acc = 0.f;
            #pragma unroll 8
            for (int a = 0; a < A_; a++)
                acc += s_q[a] * g_addrT[a*N_ + n];
            for (int s = 0; s < t; s++)
                acc += s_w[s*N_ + n] * s_d[s];
            float v = s_beta[0] * acc;
            float mx = warp_max(v);
            if (lane == 0) s_m[wl] = mx;
            __syncthreads();
            float mb = s_m[0];
            #pragma unroll
            for (int w = 1; w < 32; w++) mb = fmaxf(mb, s_m[w]);
            float e = expf(v - mb);
            float es = warp_sum(e);
            if (lane == 0) s_e[wl] = es;
            __syncthreads();
            float ss = 0.f;
            #pragma unroll
            for (int w = 0; w < 32; w++) ss += s_e[w];
            s_w[t*N_ + n] = e / ss;
        }
        __syncthreads();

        // ---- stage 4a: G_s (warp per s) + ra (warp per 2 a's) ----
        if (wl < t) {
            float g = 0.f;
            #pragma unroll 4
            for (int i = 0; i < 32; i++) {
                int nn = i*32 + lane;
                g += s_w[wl*N_ + nn] * s_w[t*N_ + nn];
            }
            g = warp_sum(g);
            if (lane == 0) s_G[wl] = g;
        }
        {
            float a0 = 0.f, a1 = 0.f;
            #pragma unroll 4
            for (int i = 0; i < 32; i++) {
                int nn = i*32 + lane;
                float wv = s_w[t*N_ + nn];
                a0 += wv * g_addrT[wl*N_ + nn];
                a1 += wv * g_addrT[(wl + 32)*N_ + nn];
            }
            a0 = warp_sum(a0);
            a1 = warp_sum(a1);
            if (lane == 0) { s_r[wl] = a0; s_r[wl + 32] = a1; }
        }
        __syncthreads();

        // ---- stage 4b: rc[c] = sum_s G_s cand_s[c] ----
        if (tid < C_) {
            float acc = 0.f;
            for (int s = 0; s < t; s++)
                acc += s_G[s] * s_cand[s*192 + tid];
            s_r[A_ + tid] = acc;
        }
        __syncthreads();

        // ---- stage 5: GRU (8 hids per warp) ----
        #pragma unroll
        for (int j = 0; j < 8; j++) {
            int hid = wl + 32*j;
            float a0, a1, a2;
            {
                const float4* w4 = (const float4*)Wm + hid*64;
                a0 = warp_sum(dot8(w4[lane], w4[32 + lane], r4[lane], r4[32 + lane]));
            }
            {
                const float4* w4 = (const float4*)Wm + (256 + hid)*64;
                a1 = warp_sum(dot8(w4[lane], w4[32 + lane], r4[lane], r4[32 + lane]));
            }
            {
                const float4* w4 = (const float4*)Wm + (512 + hid)*64;
                a2 = warp_sum(dot8(w4[lane], w4[32 + lane], r4[lane], r4[32 + lane]));
            }
            if (lane == 0) {
                float gm0 = a0 + bm[hid];
                float gm1 = a1 + bm[256 + hid];
                float gm2 = a2 + bm[512 + hid];
                float rr = 1.f / (1.f + expf(-(s_gi[hid] + s_gh[hid] + gm0)));
                float zz = 1.f / (1.f + expf(-(s_gi[256 + hid] + s_gh[256 + hid] + gm1)));
                float nn = tanhf(s_gi[512 + hid] + gm2 + rr * s_gh[512 + hid]);
                float hn = (1.f - zz)*nn + zz*s_h[hid];
                s_h[hid] = hn;
                out[t*H_*B_ + hid*32 + b] = hn;
            }
        }
        __syncthreads();
    }

    if (wl == 0) head_out(Wout, bo, s_h, out, T_ - 1, b, lane);
}

extern "C" void kernel_launch(void* const* d_in, const int* in_sizes, int n_in,
                              void* d_out, int out_size) {
    (void)in_sizes; (void)n_in; (void)out_size;
    const float* batch = (const float*)d_in[0];
    const float* Wi    = (const float*)d_in[1];
    const float* bi    = (const float*)d_in[2];
    const float* Wh    = (const float*)d_in[3];
    const float* bh    = (const float*)d_in[4];
    const float* Wm    = (const float*)d_in[5];
    const float* bm    = (const float*)d_in[6];
    const float* Wout  = (const float*)d_in[7];
    const float* bo    = (const float*)d_in[8];
    const float* addr  = (const float*)d_in[9];
    const float* Wq    = (const float*)d_in[10];
    const float* bq    = (const float*)d_in[11];
    const float* u     = (const float*)d_in[12];
    const float* Wch   = (const float*)d_in[13];
    const float* Wci   = (const float*)d_in[14];
    float* out = (float*)d_out;

    static int smem_set = 0;
    if (!smem_set) {
        cudaFuncSetAttribute((const void*)k_run,
                             cudaFuncAttributeMaxDynamicSharedMemorySize,
                             SMEM_FLOATS * 4);
        smem_set = 1;
    }
    k_init<<<1032, 256>>>(batch, addr, Wi, bi, Wci);
    k_run<<<32, 1024, SMEM_FLOATS * 4>>>(Wh, bh, Wq, bq, Wch, u, Wm, bm,
                                         Wout, bo, out);
}

// round 11
// speedup vs baseline: 1.4773x; 1.4773x over previous
#include <cuda_runtime.h>
#include <math.h>

#define B_ 32
#define T_ 32
#define F_ 64
#define H_ 256
#define N_ 1024
#define A_ 64
#define C_ 192
#define M_ 256
#define HSOFF (T_*H_*B_)

// ---------------- precomputed globals ----------------
__device__ __align__(16) float g_addrT[A_*N_];     // addrT[a*1024+n]
__device__ __align__(16) float g_giA[T_*B_*768];   // gi: [(t*32+b)*768+row]
__device__ __align__(16) float g_cxA[T_*B_*C_];    // Wci@x: [(t*32+b)*192+c]
__device__ __align__(16) float g_WhT[H_*768];      // [k*768+row]
__device__ __align__(16) float g_WqT[H_*M_];       // [k*256+m]
__device__ __align__(16) float g_WchT[H_*C_];      // [k*192+c]
__device__ __align__(16) float g_WmT[M_*768];      // [m*768+row]

__device__ __forceinline__ float warp_sum(float v) {
    #pragma unroll
    for (int o = 16; o; o >>= 1) v += __shfl_xor_sync(0xffffffffu, v, o);
    return v;
}
__device__ __forceinline__ float warp_max(float v) {
    #pragma unroll
    for (int o = 16; o; o >>= 1) v = fmaxf(v, __shfl_xor_sync(0xffffffffu, v, o));
    return v;
}
__device__ __forceinline__ float dot8(float4 w1, float4 w2, float4 h1, float4 h2) {
    return w1.x*h1.x + w1.y*h1.y + w1.z*h1.z + w1.w*h1.w
         + w2.x*h2.x + w2.y*h2.y + w2.z*h2.z + w2.w*h2.w;
}

__device__ __forceinline__ void head_out(const float* __restrict__ Wout,
                                         const float* __restrict__ bo,
                                         const float* __restrict__ s_h,
                                         float* __restrict__ out,
                                         int tstep, int b, int lane) {
    float logit[10];
    float mx = -1e30f;
    #pragma unroll
    for (int o = 0; o < 10; o++) {
        float s = 0.f;
        #pragma unroll
        for (int j = 0; j < 8; j++) {
            int k = lane + 32*j;
            s += Wout[o*H_ + k] * s_h[k];
        }
        s = warp_sum(s);
        s += bo[o];
        logit[o] = s;
        mx = fmaxf(mx, s);
    }
    float se = 0.f;
    #pragma unroll
    for (int o = 0; o < 10; o++) se += expf(logit[o] - mx);
    float lse = mx + logf(se);
    if (lane == 0) {
        #pragma unroll
        for (int o = 0; o < 10; o++)
            out[HSOFF + (tstep*10 + o)*B_ + b] = logit[o] - lse;
    }
}

// ================= K0: init (once) =================
__global__ __launch_bounds__(256, 4)
void k_init(const float* __restrict__ batch, const float* __restrict__ addr,
            const float* __restrict__ Wi, const float* __restrict__ bi,
            const float* __restrict__ Wci, const float* __restrict__ Wh,
            const float* __restrict__ Wq, const float* __restrict__ Wch,
            const float* __restrict__ Wm)
{
    int blk = blockIdx.x, tid = threadIdx.x, lane = tid & 31, wl = tid >> 5;
    if (blk < 1024) {
        int t = blk >> 5, b = blk & 31;
        __shared__ float sx[64];
        if (tid < 64) {
            int idx = tid*32 + b;          // raw-reshape: x_t[f,b] = flat[f*32+b]
            sx[tid] = batch[(idx >> 6)*(T_*F_) + t*F_ + (idx & 63)];
        }
        __syncthreads();
        for (int r = wl; r < 960; r += 8) {
            if (r < 768) {
                float acc = Wi[r*64 + lane]*sx[lane] + Wi[r*64 + 32 + lane]*sx[32 + lane];
                acc = warp_sum(acc);
                if (lane == 0) g_giA[(t*32 + b)*768 + r] = acc + bi[r];
            } else {
                int c = r - 768;
                float acc = Wci[c*64 + lane]*sx[lane] + Wci[c*64 + 32 + lane]*sx[32 + lane];
                acc = warp_sum(acc);
                if (lane == 0) g_cxA[(t*32 + b)*192 + c] = acc;
            }
        }
    } else {
        int i0 = (blk - 1024)*256 + tid;
        int STR = (gridDim.x - 1024)*256;
        for (int i = i0; i < A_*N_; i += STR)
            g_addrT[i] = addr[(i & 1023)*A_ + (i >> 10)];
        for (int i = i0; i < H_*768; i += STR)
            g_WhT[i] = Wh[(i % 768)*H_ + (i / 768)];
        for (int i = i0; i < H_*M_; i += STR)
            g_WqT[i] = Wq[(i & 255)*H_ + (i >> 8)];
        for (int i = i0; i < H_*C_; i += STR)
            g_WchT[i] = Wch[(i % 192)*H_ + (i / 192)];
        for (int i = i0; i < M_*768; i += STR)
            g_WmT[i] = Wm[(i % 768)*H_ + (i / 768)];
    }
}

// ================= K1: whole recurrence, one block per b =================
// smem layout (floats):
#define SM_W     0          // 32768 whist[32][1024]
#define SM_CAND  32768      // 6144 cand[32][192]
#define SM_GI    38912      // 768
#define SM_GHP   39680      // 1536 (gh partials, two k-halves)
#define SM_GMP   41216      // 1536 (gm partials)
#define SM_Q     42752      // 256
#define SM_H     43008      // 256
#define SM_R     43264      // 256
#define SM_D     43520      // 32
#define SM_G     43552      // 32
#define SM_M     43584      // 8
#define SM_E     43600      // 8
#define SM_BETA  43616      // 1
#define SMEM_FLOATS 43632

__global__ __launch_bounds__(1024, 1)
void k_run(const float* __restrict__ bh,  const float* __restrict__ bq,
           const float* __restrict__ uvec,const float* __restrict__ bm,
           const float* __restrict__ Wout,const float* __restrict__ bo,
           float* __restrict__ out)
{
    extern __shared__ __align__(16) float sm[];
    float* s_w    = sm + SM_W;
    float* s_cand = sm + SM_CAND;
    float* s_gi   = sm + SM_GI;
    float* s_ghp  = sm + SM_GHP;
    float* s_gmp  = sm + SM_GMP;
    float* s_q    = sm + SM_Q;
    float* s_h    = sm + SM_H;
    float* s_r    = sm + SM_R;
    float* s_d    = sm + SM_D;
    float* s_G    = sm + SM_G;
    float* s_m    = sm + SM_M;
    float* s_e    = sm + SM_E;
    float* s_beta = sm + SM_BETA;

    const int b = blockIdx.x;
    const int tid = threadIdx.x, lane = tid & 31, wl = tid >> 5;
    const float4* h4 = (const float4*)s_h;

    if (tid < 256) s_h[tid] = 0.f;
    __syncthreads();

    for (int t = 0; t < T_; t++) {
        // ========== stage 1: gi load + gh/q/cand/beta + head(t-1) ==========
        if (tid < 768) s_gi[tid] = g_giA[(t*32 + b)*768 + tid];
        if (wl < 12) {
            // gh partials: grp = wl>>1 (128 rows), khalf = wl&1
            int grp = wl >> 1, kh = wl & 1;
            int row = grp*128 + lane*4;
            int k0 = kh << 7;
            float a0 = 0.f, a1 = 0.f, a2 = 0.f, a3 = 0.f;
            #pragma unroll 8
            for (int k = k0; k < k0 + 128; k++) {
                float4 w = *(const float4*)(g_WhT + k*768 + row);
                float hk = s_h[k];
                a0 += w.x*hk; a1 += w.y*hk; a2 += w.z*hk; a3 += w.w*hk;
            }
            float* dst = s_ghp + kh*768 + row;
            dst[0] = a0; dst[1] = a1; dst[2] = a2; dst[3] = a3;
        } else if (wl < 14) {
            // q: 2 warps x 128 rows, full k
            int m0 = (wl - 12)*128 + lane*4;
            float a0 = 0.f, a1 = 0.f, a2 = 0.f, a3 = 0.f;
            #pragma unroll 8
            for (int k = 0; k < 256; k++) {
                float4 w = *(const float4*)(g_WqT + k*256 + m0);
                float hk = s_h[k];
                a0 += w.x*hk; a1 += w.y*hk; a2 += w.z*hk; a3 += w.w*hk;
            }
            float4 bq4 = *(const float4*)(bq + m0);
            s_q[m0    ] = a0 + bq4.x;
            s_q[m0 + 1] = a1 + bq4.y;
            s_q[m0 + 2] = a2 + bq4.z;
            s_q[m0 + 3] = a3 + bq4.w;
        } else if (wl < 16) {
            // cand: warp 14: c 0..127, warp 15: c 128..191 (lanes <16)
            int c0 = (wl - 14)*128 + lane*4;
            if (c0 < C_) {
                float a0 = 0.f, a1 = 0.f, a2 = 0.f, a3 = 0.f;
                #pragma unroll 8
                for (int k = 0; k < 256; k++) {
                    float4 w = *(const float4*)(g_WchT + k*192 + c0);
                    float hk = s_h[k];
                    a0 += w.x*hk; a1 += w.y*hk; a2 += w.z*hk; a3 += w.w*hk;
                }
                float4 cx = *(const float4*)(g_cxA + (t*32 + b)*192 + c0);
                float* cd = s_cand + t*192 + c0;
                cd[0] = fmaxf(a0 + cx.x, 0.f);
                cd[1] = fmaxf(a1 + cx.y, 0.f);
                cd[2] = fmaxf(a2 + cx.z, 0.f);
                cd[3] = fmaxf(a3 + cx.w, 0.f);
            }
        } else if (wl == 16) {
            const float4* u4 = (const float4*)uvec;
            float acc = dot8(u4[lane], u4[32 + lane], h4[lane], h4[32 + lane]);
            acc = warp_sum(acc);
            if (lane == 0) {
                float sp = (acc > 0.f) ? acc + log1pf(expf(-acc)) : log1pf(expf(acc));
                s_beta[0] = sp + 1.f;
            }
        } else if (wl == 17) {
            if (t > 0) head_out(Wout, bo, s_h, out, t - 1, b, lane);
        }
        __syncthreads();

        // ========== stage 2: d_s = cand_s . q_c (warp per s < t) ==========
        if (wl < t) {
            float acc = 0.f;
            #pragma unroll
            for (int j = 0; j < 6; j++) {
                int c = lane + 32*j;
                acc += s_cand[wl*192 + c] * s_q[A_ + c];
            }
            acc = warp_sum(acc);
            if (lane == 0) s_d[wl] = acc;
        }
        __syncthreads();

        // ========== stage 3: sim (4 n per thread) + block softmax ==========
        {
            const bool act = tid < 256;
            float v0, v1, v2, v3;
            if (act) {
                const float4* at4 = (const float4*)g_addrT;
                float4 acc = make_float4(0.f, 0.f, 0.f, 0.f);
                #pragma unroll 8
                for (int a = 0; a < A_; a++) {
                    float4 av = at4[a*256 + tid];
                    float qa = s_q[a];
                    acc.x += qa*av.x; acc.y += qa*av.y;
                    acc.z += qa*av.z; acc.w += qa*av.w;
                }
                for (int s = 0; s < t; s++) {
                    float4 wv = *(const float4*)(s_w + s*N_ + tid*4);
                    float ds = s_d[s];
                    acc.x += ds*wv.x; acc.y += ds*wv.y;
                    acc.z += ds*wv.z; acc.w += ds*wv.w;
                }
                float bsc = s_beta[0];
                v0 = bsc*acc.x; v1 = bsc*acc.y; v2 = bsc*acc.z; v3 = bsc*acc.w;
                float mx = fmaxf(fmaxf(v0, v1), fmaxf(v2, v3));
                mx = warp_max(mx);
                if (lane == 0) s_m[wl] = mx;
            }
            __syncthreads();
            float mb = s_m[0];
            #pragma unroll
            for (int w = 1; w < 8; w++) mb = fmaxf(mb, s_m[w]);
            float e0, e1, e2, e3;
            if (act) {
                e0 = expf(v0 - mb); e1 = expf(v1 - mb);
                e2 = expf(v2 - mb); e3 = expf(v3 - mb);
                float es = warp_sum(e0 + e1 + e2 + e3);
                if (lane == 0) s_e[wl] = es;
            }
            __syncthreads();
            if (act) {
                float ss = 0.f;
                #pragma unroll
                for (int w = 0; w < 8; w++) ss += s_e[w];
                float li = 1.f / ss;
                float4 wv = make_float4(e0*li, e1*li, e2*li, e3*li);
                *(float4*)(s_w + t*N_ + tid*4) = wv;
            }
        }
        __syncthreads();

        // ========== stage 4a: G_s (warp per s) + ra (warp per 2 a's) ==========
        if (wl < t) {
            const float4* wsp = (const float4*)(s_w + wl*N_);
            const float4* wtp = (const float4*)(s_w + t*N_);
            float g = 0.f;
            #pragma unroll
            for (int j = 0; j < 8; j++) {
                float4 a_ = wsp[j*32 + lane];
                float4 c_ = wtp[j*32 + lane];
                g += a_.x*c_.x + a_.y*c_.y + a_.z*c_.z + a_.w*c_.w;
            }
            g = warp_sum(g);
            if (lane == 0) s_G[wl] = g;
        }
        {
            const float4* at4 = (const float4*)g_addrT;
            const float4* wtp = (const float4*)(s_w + t*N_);
            float a0 = 0.f, a1 = 0.f;
            #pragma unroll
            for (int j = 0; j < 8; j++) {
                float4 wv = wtp[j*32 + lane];
                float4 r0 = at4[wl*256 + j*32 + lane];
                float4 r1 = at4[(wl + 32)*256 + j*32 + lane];
                a0 += wv.x*r0.x + wv.y*r0.y + wv.z*r0.z + wv.w*r0.w;
                a1 += wv.x*r1.x + wv.y*r1.y + wv.z*r1.z + wv.w*r1.w;
            }
            a0 = warp_sum(a0);
            a1 = warp_sum(a1);
            if (lane == 0) { s_r[wl] = a0; s_r[wl + 32] = a1; }
        }
        __syncthreads();

        // ========== stage 4b: rc[c] = sum_s G_s cand_s[c] ==========
        if (tid < C_) {
            float acc = 0.f;
            for (int s = 0; s < t; s++)
                acc += s_G[s] * s_cand[s*192 + tid];
            s_r[A_ + tid] = acc;
        }
        __syncthreads();

        // ========== stage 5: gm partials (12 warps, split-k) ==========
        if (wl < 12) {
            int grp = wl >> 1, kh = wl & 1;
            int row = grp*128 + lane*4;
            int m0 = kh << 7;
            float a0 = 0.f, a1 = 0.f, a2 = 0.f, a3 = 0.f;
            #pragma unroll 8
            for (int m = m0; m < m0 + 128; m++) {
                float4 w = *(const float4*)(g_WmT + m*768 + row);
                float rm = s_r[m];
                a0 += w.x*rm; a1 += w.y*rm; a2 += w.z*rm; a3 += w.w*rm;
            }
            float* dst = s_gmp + kh*768 + row;
            dst[0] = a0; dst[1] = a1; dst[2] = a2; dst[3] = a3;
        }
        __syncthreads();

        // ========== stage 5b: gate combine + h update ==========
        if (tid < 256) {
            int hid = tid;
            float ghr = s_ghp[hid      ] + s_ghp[768 + hid      ] + bh[hid];
            float ghz = s_ghp[256 + hid] + s_ghp[768 + 256 + hid] + bh[256 + hid];
            float ghn = s_ghp[512 + hid] + s_ghp[768 + 512 + hid] + bh[512 + hid];
            float gmr = s_gmp[hid      ] + s_gmp[768 + hid      ] + bm[hid];
            float gmz = s_gmp[256 + hid] + s_gmp[768 + 256 + hid] + bm[256 + hid];
            float gmn = s_gmp[512 + hid] + s_gmp[768 + 512 + hid] + bm[512 + hid];
            float rr = 1.f / (1.f + expf(-(s_gi[hid] + ghr + gmr)));
            float zz = 1.f / (1.f + expf(-(s_gi[256 + hid] + ghz + gmz)));
            float nn = tanhf(s_gi[512 + hid] + gmn + rr*ghn);
            float hn = (1.f - zz)*nn + zz*s_h[hid];
            s_h[hid] = hn;
            out[t*H_*B_ + hid*32 + b] = hn;
        }
        __syncthreads();
    }

    if (wl == 0) head_out(Wout, bo, s_h, out, T_ - 1, b, lane);
}

extern "C" void kernel_launch(void* const* d_in, const int* in_sizes, int n_in,
                              void* d_out, int out_size) {
    (void)in_sizes; (void)n_in; (void)out_size;
    const float* batch = (const float*)d_in[0];
    const float* Wi    = (const float*)d_in[1];
    const float* bi    = (const float*)d_in[2];
    const float* Wh    = (const float*)d_in[3];
    const float* bh    = (const float*)d_in[4];
    const float* Wm    = (const float*)d_in[5];
    const float* bm    = (const float*)d_in[6];
    const float* Wout  = (const float*)d_in[7];
    const float* bo    = (const float*)d_in[8];
    const float* addr  = (const float*)d_in[9];
    const float* Wq    = (const float*)d_in[10];
    const float* bq    = (const float*)d_in[11];
    const float* u     = (const float*)d_in[12];
    const float* Wch   = (const float*)d_in[13];
    const float* Wci   = (const float*)d_in[14];
    float* out = (float*)d_out;

    static int smem_set = 0;
    if (!smem_set) {
        cudaFuncSetAttribute((const void*)k_run,
                             cudaFuncAttributeMaxDynamicSharedMemorySize,
                             SMEM_FLOATS * 4);
        smem_set = 1;
    }
    k_init<<<1536, 256>>>(batch, addr, Wi, bi, Wci, Wh, Wq, Wch, Wm);
    k_run<<<32, 1024, SMEM_FLOATS * 4>>>(bh, bq, u, bm, Wout, bo, out);
}

// round 12
// speedup vs baseline: 1.6593x; 1.1232x over previous
#include <cuda_runtime.h>
#include <math.h>

#define B_ 32
#define T_ 32
#define F_ 64
#define H_ 256
#define N_ 1024
#define A_ 64
#define C_ 192
#define M_ 256
#define HSOFF (T_*H_*B_)

// ---------------- precomputed globals ----------------
__device__ __align__(16) float g_addrT[A_*N_];     // addrT[a*1024+n]
__device__ __align__(16) float g_giA[T_*B_*768];   // gi: [(t*32+b)*768+row]
__device__ __align__(16) float g_cxA[T_*B_*C_];    // Wci@x: [(t*32+b)*192+c]
__device__ __align__(16) float g_WhT[H_*768];      // [k*768+row]
__device__ __align__(16) float g_WqT[H_*M_];       // [k*256+m]
__device__ __align__(16) float g_WchT[H_*C_];      // [k*192+c]
__device__ __align__(16) float g_WmT[M_*768];      // [m*768+row]

__device__ __forceinline__ float warp_sum(float v) {
    #pragma unroll
    for (int o = 16; o; o >>= 1) v += __shfl_xor_sync(0xffffffffu, v, o);
    return v;
}
__device__ __forceinline__ float warp_max(float v) {
    #pragma unroll
    for (int o = 16; o; o >>= 1) v = fmaxf(v, __shfl_xor_sync(0xffffffffu, v, o));
    return v;
}
__device__ __forceinline__ float dot8(float4 w1, float4 w2, float4 h1, float4 h2) {
    return w1.x*h1.x + w1.y*h1.y + w1.z*h1.z + w1.w*h1.w
         + w2.x*h2.x + w2.y*h2.y + w2.z*h2.z + w2.w*h2.w;
}

// ================= K0: init (once) =================
__global__ __launch_bounds__(256, 4)
void k_init(const float* __restrict__ batch, const float* __restrict__ addr,
            const float* __restrict__ Wi, const float* __restrict__ bi,
            const float* __restrict__ Wci, const float* __restrict__ Wh,
            const float* __restrict__ Wq, const float* __restrict__ Wch,
            const float* __restrict__ Wm)
{
    int blk = blockIdx.x, tid = threadIdx.x, lane = tid & 31, wl = tid >> 5;
    if (blk < 1024) {
        int t = blk >> 5, b = blk & 31;
        __shared__ float sx[64];
        if (tid < 64) {
            int idx = tid*32 + b;          // raw-reshape: x_t[f,b] = flat[f*32+b]
            sx[tid] = batch[(idx >> 6)*(T_*F_) + t*F_ + (idx & 63)];
        }
        __syncthreads();
        for (int r = wl; r < 960; r += 8) {
            if (r < 768) {
                float acc = Wi[r*64 + lane]*sx[lane] + Wi[r*64 + 32 + lane]*sx[32 + lane];
                acc = warp_sum(acc);
                if (lane == 0) g_giA[(t*32 + b)*768 + r] = acc + bi[r];
            } else {
                int c = r - 768;
                float acc = Wci[c*64 + lane]*sx[lane] + Wci[c*64 + 32 + lane]*sx[32 + lane];
                acc = warp_sum(acc);
                if (lane == 0) g_cxA[(t*32 + b)*192 + c] = acc;
            }
        }
    } else {
        int i0 = (blk - 1024)*256 + tid;
        int STR = (gridDim.x - 1024)*256;
        for (int i = i0; i < A_*N_; i += STR)
            g_addrT[i] = addr[(i & 1023)*A_ + (i >> 10)];
        for (int i = i0; i < H_*768; i += STR)
            g_WhT[i] = Wh[(i % 768)*H_ + (i / 768)];
        for (int i = i0; i < H_*M_; i += STR)
            g_WqT[i] = Wq[(i & 255)*H_ + (i >> 8)];
        for (int i = i0; i < H_*C_; i += STR)
            g_WchT[i] = Wch[(i % 192)*H_ + (i / 192)];
        for (int i = i0; i < M_*768; i += STR)
            g_WmT[i] = Wm[(i % 768)*H_ + (i / 768)];
    }
}

// ================= smem layout (floats) =================
#define SM_W     0          // 32768  whist[32][1024]
#define SM_CAND  32768      // 6144   cand[32][192]
#define SM_GI    38912      // 768
#define SM_GHP   39680      // 3072   gh partials (4 kq)
#define SM_GMP   42752      // 3072   gm partials (4 kq)
#define SM_QP    45824      // 512    q partials (2 kh)
#define SM_CP    46336      // 384    cand partials (2 kh)
#define SM_Q     46720      // 256
#define SM_H     46976      // 256
#define SM_R     47232      // 256
#define SM_BH    47488      // 768
#define SM_BM    48256      // 768
#define SM_BQ    49024      // 256
#define SM_U     49280      // 256
#define SM_WOUT  49536      // 2560
#define SM_BO    52096      // 16
#define SM_D     52112      // 32
#define SM_G     52144      // 32
#define SM_MX    52176      // 32
#define SM_E     52208      // 32
#define SM_BETA  52240      // 4
#define SMEM_FLOATS 52256

__global__ __launch_bounds__(1024, 1)
void k_run(const float* __restrict__ bh,  const float* __restrict__ bq,
           const float* __restrict__ uvec,const float* __restrict__ bm,
           const float* __restrict__ Wout,const float* __restrict__ bo,
           float* __restrict__ out)
{
    extern __shared__ __align__(16) float sm[];
    float* s_w    = sm + SM_W;
    float* s_cand = sm + SM_CAND;
    float* s_gi   = sm + SM_GI;
    float* s_ghp  = sm + SM_GHP;
    float* s_gmp  = sm + SM_GMP;
    float* s_qp   = sm + SM_QP;
    float* s_cp   = sm + SM_CP;
    float* s_q    = sm + SM_Q;
    float* s_h    = sm + SM_H;
    float* s_r    = sm + SM_R;
    float* s_bh   = sm + SM_BH;
    float* s_bm   = sm + SM_BM;
    float* s_bq   = sm + SM_BQ;
    float* s_u    = sm + SM_U;
    float* s_Wout = sm + SM_WOUT;
    float* s_bo   = sm + SM_BO;
    float* s_d    = sm + SM_D;
    float* s_G    = sm + SM_G;
    float* s_mx   = sm + SM_MX;
    float* s_e    = sm + SM_E;
    float* s_beta = sm + SM_BETA;

    const int b = blockIdx.x;
    const int tid = threadIdx.x, lane = tid & 31, wl = tid >> 5;
    const float4* h4 = (const float4*)s_h;

    // ---- one-time staging ----
    if (tid < 768) { s_bh[tid] = bh[tid]; s_bm[tid] = bm[tid]; }
    if (tid < 256) { s_bq[tid] = bq[tid]; s_u[tid] = uvec[tid]; s_h[tid] = 0.f; }
    for (int i = tid; i < 2560; i += 1024) s_Wout[i] = Wout[i];
    if (tid < 10) s_bo[tid] = bo[tid];
    __syncthreads();

    for (int t = 0; t < T_; t++) {
        // ========== S1: gh(24w) + q(4w) + cand(4w) partials ==========
        if (wl < 24) {
            int grp = wl >> 2, kq = wl & 3;
            int row = grp*128 + lane*4;
            int k0 = kq << 6;
            float a0 = 0.f, a1 = 0.f, a2 = 0.f, a3 = 0.f;
            #pragma unroll 8
            for (int k = k0; k < k0 + 64; k++) {
                float4 w = *(const float4*)(g_WhT + k*768 + row);
                float hk = s_h[k];
                a0 += w.x*hk; a1 += w.y*hk; a2 += w.z*hk; a3 += w.w*hk;
            }
            float* dst = s_ghp + kq*768 + row;
            dst[0] = a0; dst[1] = a1; dst[2] = a2; dst[3] = a3;
        } else if (wl < 28) {
            int idx = wl - 24, grp = idx >> 1, kh = idx & 1;
            int m0 = grp*128 + lane*4;
            int k0 = kh << 7;
            float a0 = 0.f, a1 = 0.f, a2 = 0.f, a3 = 0.f;
            #pragma unroll 8
            for (int k = k0; k < k0 + 128; k++) {
                float4 w = *(const float4*)(g_WqT + k*256 + m0);
                float hk = s_h[k];
                a0 += w.x*hk; a1 += w.y*hk; a2 += w.z*hk; a3 += w.w*hk;
            }
            float* dst = s_qp + kh*256 + m0;
            dst[0] = a0; dst[1] = a1; dst[2] = a2; dst[3] = a3;
        } else {
            int idx = wl - 28, cg = idx >> 1, kh = idx & 1;
            if (lane < 24) {
                int c0 = cg*96 + lane*4;
                int k0 = kh << 7;
                float a0 = 0.f, a1 = 0.f, a2 = 0.f, a3 = 0.f;
                #pragma unroll 8
                for (int k = k0; k < k0 + 128; k++) {
                    float4 w = *(const float4*)(g_WchT + k*192 + c0);
                    float hk = s_h[k];
                    a0 += w.x*hk; a1 += w.y*hk; a2 += w.z*hk; a3 += w.w*hk;
                }
                float* dst = s_cp + kh*192 + c0;
                dst[0] = a0; dst[1] = a1; dst[2] = a2; dst[3] = a3;
            }
        }
        __syncthreads();

        // ========== S2: gi load + q combine + cand combine + head(t-1) ==========
        if (tid < 768) s_gi[tid] = g_giA[(t*32 + b)*768 + tid];
        if (tid < 256) {
            s_q[tid] = s_qp[tid] + s_qp[256 + tid] + s_bq[tid];
        } else if (wl == 8) {
            // head for t-1 (uses s_h = h_{t-1} post-update)
            if (t > 0) {
                float logit[10];
                float mx = -1e30f;
                #pragma unroll
                for (int o = 0; o < 10; o++) {
                    float s = 0.f;
                    #pragma unroll
                    for (int j = 0; j < 8; j++) {
                        int k = lane + 32*j;
                        s += s_Wout[o*H_ + k] * s_h[k];
                    }
                    s = warp_sum(s);
                    s += s_bo[o];
                    logit[o] = s;
                    mx = fmaxf(mx, s);
                }
                float se = 0.f;
                #pragma unroll
                for (int o = 0; o < 10; o++) se += expf(logit[o] - mx);
                float lse = mx + logf(se);
                if (lane == 0) {
                    #pragma unroll
                    for (int o = 0; o < 10; o++)
                        out[HSOFF + ((t-1)*10 + o)*B_ + b] = logit[o] - lse;
                }
            }
        } else if (tid >= 288 && tid < 480) {
            int c = tid - 288;
            float cx = g_cxA[(t*32 + b)*192 + c];
            s_cand[t*192 + c] = fmaxf(s_cp[c] + s_cp[192 + c] + cx, 0.f);
        }
        __syncthreads();

        // ========== S3: d_s (warps 0..t-1) + beta (warp 31) ==========
        if (wl < t) {
            float acc = 0.f;
            #pragma unroll
            for (int j = 0; j < 6; j++) {
                int c = lane + 32*j;
                acc += s_cand[wl*192 + c] * s_q[A_ + c];
            }
            acc = warp_sum(acc);
            if (lane == 0) s_d[wl] = acc;
        } else if (wl == 31) {
            const float4* u4 = (const float4*)s_u;
            float acc = dot8(u4[lane], u4[32 + lane], h4[lane], h4[32 + lane]);
            acc = warp_sum(acc);
            if (lane == 0) {
                float sp = (acc > 0.f) ? acc + log1pf(expf(-acc)) : log1pf(expf(acc));
                s_beta[0] = sp + 1.f;
            }
        }
        __syncthreads();

        // ========== S4: sim (thread per n) + block softmax -> w ==========
        {
            int n = tid;
            float acc = 0.f;
            #pragma unroll 8
            for (int a = 0; a < A_; a++)
                acc += s_q[a] * g_addrT[a*N_ + n];
            for (int s = 0; s < t; s++)
                acc += s_w[s*N_ + n] * s_d[s];
            float v = s_beta[0] * acc;
            float mx = warp_max(v);
            if (lane == 0) s_mx[wl] = mx;
            __syncthreads();
            float mb = s_mx[0];
            #pragma unroll
            for (int w = 1; w < 32; w++) mb = fmaxf(mb, s_mx[w]);
            float e = expf(v - mb);
            float es = warp_sum(e);
            if (lane == 0) s_e[wl] = es;
            __syncthreads();
            float ss = 0.f;
            #pragma unroll
            for (int w = 0; w < 32; w++) ss += s_e[w];
            s_w[t*N_ + n] = e / ss;
        }
        __syncthreads();

        // ========== S5: G_s (warps < t) + ra (all warps) ==========
        if (wl < t) {
            const float4* wsp = (const float4*)(s_w + wl*N_);
            const float4* wtp = (const float4*)(s_w + t*N_);
            float g = 0.f;
            #pragma unroll
            for (int j = 0; j < 8; j++) {
                float4 a_ = wsp[j*32 + lane];
                float4 c_ = wtp[j*32 + lane];
                g += a_.x*c_.x + a_.y*c_.y + a_.z*c_.z + a_.w*c_.w;
            }
            g = warp_sum(g);
            if (lane == 0) s_G[wl] = g;
        }
        {
            const float4* at4 = (const float4*)g_addrT;
            const float4* wtp = (const float4*)(s_w + t*N_);
            float a0 = 0.f, a1 = 0.f;
            #pragma unroll
            for (int j = 0; j < 8; j++) {
                float4 wv = wtp[j*32 + lane];
                float4 r0 = at4[wl*256 + j*32 + lane];
                float4 r1 = at4[(wl + 32)*256 + j*32 + lane];
                a0 += wv.x*r0.x + wv.y*r0.y + wv.z*r0.z + wv.w*r0.w;
                a1 += wv.x*r1.x + wv.y*r1.y + wv.z*r1.z + wv.w*r1.w;
            }
            a0 = warp_sum(a0);
            a1 = warp_sum(a1);
            if (lane == 0) { s_r[wl] = a0; s_r[wl + 32] = a1; }
        }
        __syncthreads();

        // ========== S6: rc[c] ==========
        if (tid < C_) {
            float acc = 0.f;
            for (int s = 0; s < t; s++)
                acc += s_G[s] * s_cand[s*192 + tid];
            s_r[A_ + tid] = acc;
        }
        __syncthreads();

        // ========== S7: gm partials (24 warps, 4-way split-k) ==========
        if (wl < 24) {
            int grp = wl >> 2, kq = wl & 3;
            int row = grp*128 + lane*4;
            int m0 = kq << 6;
            float a0 = 0.f, a1 = 0.f, a2 = 0.f, a3 = 0.f;
            #pragma unroll 8
            for (int m = m0; m < m0 + 64; m++) {
                float4 w = *(const float4*)(g_WmT + m*768 + row);
                float rm = s_r[m];
                a0 += w.x*rm; a1 += w.y*rm; a2 += w.z*rm; a3 += w.w*rm;
            }
            float* dst = s_gmp + kq*768 + row;
            dst[0] = a0; dst[1] = a1; dst[2] = a2; dst[3] = a3;
        }
        __syncthreads();

        // ========== S8: gate combine + h update + out ==========
        if (tid < 256) {
            int hid = tid;
            float ghr = s_ghp[hid] + s_ghp[768 + hid] + s_ghp[1536 + hid] + s_ghp[2304 + hid] + s_bh[hid];
            float ghz = s_ghp[256 + hid] + s_ghp[768 + 256 + hid] + s_ghp[1536 + 256 + hid] + s_ghp[2304 + 256 + hid] + s_bh[256 + hid];
            float ghn = s_ghp[512 + hid] + s_ghp[768 + 512 + hid] + s_ghp[1536 + 512 + hid] + s_ghp[2304 + 512 + hid] + s_bh[512 + hid];
            float gmr = s_gmp[hid] + s_gmp[768 + hid] + s_gmp[1536 + hid] + s_gmp[2304 + hid] + s_bm[hid];
            float gmz = s_gmp[256 + hid] + s_gmp[768 + 256 + hid] + s_gmp[1536 + 256 + hid] + s_gmp[2304 + 256 + hid] + s_bm[256 + hid];
            float gmn = s_gmp[512 + hid] + s_gmp[768 + 512 + hid] + s_gmp[1536 + 512 + hid] + s_gmp[2304 + 512 + hid] + s_bm[512 + hid];
            float rr = 1.f / (1.f + expf(-(s_gi[hid] + ghr + gmr)));
            float zz = 1.f / (1.f + expf(-(s_gi[256 + hid] + ghz + gmz)));
            float nn = tanhf(s_gi[512 + hid] + gmn + rr*ghn);
            float hn = (1.f - zz)*nn + zz*s_h[hid];
            s_h[hid] = hn;
            out[t*H_*B_ + hid*32 + b] = hn;
        }
        __syncthreads();
    }

    // final head (t = T-1)
    if (wl == 0) {
        float logit[10];
        float mx = -1e30f;
        #pragma unroll
        for (int o = 0; o < 10; o++) {
            float s = 0.f;
            #pragma unroll
            for (int j = 0; j < 8; j++) {
                int k = lane + 32*j;
                s += s_Wout[o*H_ + k] * s_h[k];
            }
            s = warp_sum(s);
            s += s_bo[o];
            logit[o] = s;
            mx = fmaxf(mx, s);
        }
        float se = 0.f;
        #pragma unroll
        for (int o = 0; o < 10; o++) se += expf(logit[o] - mx);
        float lse = mx + logf(se);
        if (lane == 0) {
            #pragma unroll
            for (int o = 0; o < 10; o++)
                out[HSOFF + ((T_-1)*10 + o)*B_ + b] = logit[o] - lse;
        }
    }
}

extern "C" void kernel_launch(void* const* d_in, const int* in_sizes, int n_in,
                              void* d_out, int out_size) {
    (void)in_sizes; (void)n_in; (void)out_size;
    const float* batch = (const float*)d_in[0];
    const float* Wi    = (const float*)d_in[1];
    const float* bi    = (const float*)d_in[2];
    const float* Wh    = (const float*)d_in[3];
    const float* bh    = (const float*)d_in[4];
    const float* Wm    = (const float*)d_in[5];
    const float* bm    = (const float*)d_in[6];
    const float* Wout  = (const float*)d_in[7];
    const float* bo    = (const float*)d_in[8];
    const float* addr  = (const float*)d_in[9];
    const float* Wq    = (const float*)d_in[10];
    const float* bq    = (const float*)d_in[11];
    const float* u     = (const float*)d_in[12];
    const float* Wch   = (const float*)d_in[13];
    const float* Wci   = (const float*)d_in[14];
    float* out = (float*)d_out;

    static int smem_set = 0;
    if (!smem_set) {
        cudaFuncSetAttribute((const void*)k_run,
                             cudaFuncAttributeMaxDynamicSharedMemorySize,
                             SMEM_FLOATS * 4);
        smem_set = 1;
    }
    k_init<<<1536, 256>>>(batch, addr, Wi, bi, Wci, Wh, Wq, Wch, Wm);
    k_run<<<32, 1024, SMEM_FLOATS * 4>>>(bh, bq, u, bm, Wout, bo, out);
}

// round 13
// speedup vs baseline: 2.1552x; 1.2988x over previous
#include <cuda_runtime.h>
#include <cooperative_groups.h>
#include <math.h>

namespace cg = cooperative_groups;

#define B_ 32
#define T_ 32
#define F_ 64
#define H_ 256
#define N_ 1024
#define A_ 64
#define C_ 192
#define M_ 256
#define HSOFF (T_*H_*B_)

// ---------------- precomputed globals ----------------
__device__ __align__(16) float g_addrT[A_*N_];     // addrT[a*1024+n]
__device__ __align__(16) float g_giA[T_*B_*768];   // gi: [(t*32+b)*768+row]
__device__ __align__(16) float g_cxA[T_*B_*C_];    // Wci@x: [(t*32+b)*192+c]
__device__ __align__(16) float g_WhT[H_*768];      // [k*768+row]
__device__ __align__(16) float g_WqT[H_*M_];       // [k*256+m]
__device__ __align__(16) float g_WchT[H_*C_];      // [k*192+c]
__device__ __align__(16) float g_WmT[M_*768];      // [m*768+row]

__device__ __forceinline__ float warp_sum(float v) {
    #pragma unroll
    for (int o = 16; o; o >>= 1) v += __shfl_xor_sync(0xffffffffu, v, o);
    return v;
}
__device__ __forceinline__ float warp_max(float v) {
    #pragma unroll
    for (int o = 16; o; o >>= 1) v = fmaxf(v, __shfl_xor_sync(0xffffffffu, v, o));
    return v;
}
__device__ __forceinline__ float dot8(float4 w1, float4 w2, float4 h1, float4 h2) {
    return w1.x*h1.x + w1.y*h1.y + w1.z*h1.z + w1.w*h1.w
         + w2.x*h2.x + w2.y*h2.y + w2.z*h2.z + w2.w*h2.w;
}

// ================= K0: init (once) =================
__global__ __launch_bounds__(256, 4)
void k_init(const float* __restrict__ batch, const float* __restrict__ addr,
            const float* __restrict__ Wi, const float* __restrict__ bi,
            const float* __restrict__ Wci, const float* __restrict__ Wh,
            const float* __restrict__ Wq, const float* __restrict__ Wch,
            const float* __restrict__ Wm)
{
    int blk = blockIdx.x, tid = threadIdx.x, lane = tid & 31, wl = tid >> 5;
    if (blk < 1024) {
        int t = blk >> 5, b = blk & 31;
        __shared__ float sx[64];
        if (tid < 64) {
            int idx = tid*32 + b;          // raw-reshape: x_t[f,b] = flat[f*32+b]
            sx[tid] = batch[(idx >> 6)*(T_*F_) + t*F_ + (idx & 63)];
        }
        __syncthreads();
        for (int r = wl; r < 960; r += 8) {
            if (r < 768) {
                float acc = Wi[r*64 + lane]*sx[lane] + Wi[r*64 + 32 + lane]*sx[32 + lane];
                acc = warp_sum(acc);
                if (lane == 0) g_giA[(t*32 + b)*768 + r] = acc + bi[r];
            } else {
                int c = r - 768;
                float acc = Wci[c*64 + lane]*sx[lane] + Wci[c*64 + 32 + lane]*sx[32 + lane];
                acc = warp_sum(acc);
                if (lane == 0) g_cxA[(t*32 + b)*192 + c] = acc;
            }
        }
    } else {
        int i0 = (blk - 1024)*256 + tid;
        int STR = (gridDim.x - 1024)*256;
        for (int i = i0; i < A_*N_; i += STR)
            g_addrT[i] = addr[(i & 1023)*A_ + (i >> 10)];
        for (int i = i0; i < H_*768; i += STR)
            g_WhT[i] = Wh[(i % 768)*H_ + (i / 768)];
        for (int i = i0; i < H_*M_; i += STR)
            g_WqT[i] = Wq[(i & 255)*H_ + (i >> 8)];
        for (int i = i0; i < H_*C_; i += STR)
            g_WchT[i] = Wch[(i % 192)*H_ + (i / 192)];
        for (int i = i0; i < M_*768; i += STR)
            g_WmT[i] = Wm[(i % 768)*H_ + (i / 768)];
    }
}

// ================= smem layout (floats) =================
#define SM_W     0          // 32768  whist[32][1024] (full, replicated)
#define SM_CAND  32768      // 6144   cand[32][192]   (full via exchange)
#define SM_GI    38912      // 384    gi local rows [g*128+j]
#define SM_GHP   39296      // 3072   gh partials (8 kq x 384)
#define SM_GMP   42368      // 3072   gm partials
#define SM_QP    45440      // 512    q partials (4 kq x 128)
#define SM_CP    45952      // 384    cand partials (4 kq x 96)
#define SM_Q     46336      // 256    full q (exchange)
#define SM_H     46592      // 256    full h (exchange)
#define SM_R     46848      // 256
#define SM_BH    47104      // 384    local bh rows
#define SM_BM    47488      // 384
#define SM_BQ    47872      // 128    local half
#define SM_U     48000      // 256
#define SM_WOUT  48256      // 2560
#define SM_BO    50816      // 16
#define SM_D     50832      // 32
#define SM_G     50864      // 32
#define SM_MX    50896      // 32
#define SM_E     50928      // 32
#define SM_BETA  50960      // 4
#define SMEM_FLOATS 50976

__global__ __launch_bounds__(1024, 1) __cluster_dims__(2, 1, 1)
void k_run(const float* __restrict__ bh,  const float* __restrict__ bq,
           const float* __restrict__ uvec,const float* __restrict__ bm,
           const float* __restrict__ Wout,const float* __restrict__ bo,
           float* __restrict__ out)
{
    extern __shared__ __align__(16) float sm[];
    float* s_w    = sm + SM_W;
    float* s_cand = sm + SM_CAND;
    float* s_gi   = sm + SM_GI;
    float* s_ghp  = sm + SM_GHP;
    float* s_gmp  = sm + SM_GMP;
    float* s_qp   = sm + SM_QP;
    float* s_cp   = sm + SM_CP;
    float* s_q    = sm + SM_Q;
    float* s_h    = sm + SM_H;
    float* s_r    = sm + SM_R;
    float* s_bh   = sm + SM_BH;
    float* s_bm   = sm + SM_BM;
    float* s_bq   = sm + SM_BQ;
    float* s_u    = sm + SM_U;
    float* s_Wout = sm + SM_WOUT;
    float* s_bo   = sm + SM_BO;
    float* s_d    = sm + SM_D;
    float* s_G    = sm + SM_G;
    float* s_mx   = sm + SM_MX;
    float* s_e    = sm + SM_E;
    float* s_beta = sm + SM_BETA;

    cg::cluster_group cl = cg::this_cluster();
    const unsigned rank = cl.block_rank();
    const unsigned peer = rank ^ 1u;
    float* p_q    = (float*)cl.map_shared_rank((void*)s_q, peer);
    float* p_cand = (float*)cl.map_shared_rank((void*)s_cand, peer);
    float* p_h    = (float*)cl.map_shared_rank((void*)s_h, peer);

    const int b = blockIdx.x >> 1;
    const int r = (int)rank;
    const int tid = threadIdx.x, lane = tid & 31, wl = tid >> 5;
    const float4* h4 = (const float4*)s_h;

    // ---- one-time staging ----
    if (tid < 384) {
        int g = tid >> 7, j = tid & 127;
        s_bh[tid] = bh[g*256 + r*128 + j];
        s_bm[tid] = bm[g*256 + r*128 + j];
    }
    if (tid < 128) s_bq[tid] = bq[r*128 + tid];
    if (tid < 256) { s_u[tid] = uvec[tid]; s_h[tid] = 0.f; }
    for (int i = tid; i < 2560; i += 1024) s_Wout[i] = Wout[i];
    if (tid < 10) s_bo[tid] = bo[tid];
    __syncthreads();
    cl.sync();

    for (int t = 0; t < T_; t++) {
        // ===== S1: gh(24w) + q(4w) + cand(4w) partials — r's row halves =====
        if (wl < 24) {
            int g = wl >> 3, kq = wl & 7;
            int row = g*256 + r*128 + lane*4;
            int k0 = kq << 5;
            float a0 = 0.f, a1 = 0.f, a2 = 0.f, a3 = 0.f;
            #pragma unroll 8
            for (int k = k0; k < k0 + 32; k++) {
                float4 w = *(const float4*)(g_WhT + k*768 + row);
                float hk = s_h[k];
                a0 += w.x*hk; a1 += w.y*hk; a2 += w.z*hk; a3 += w.w*hk;
            }
            float* dst = s_ghp + kq*384 + g*128 + lane*4;
            dst[0] = a0; dst[1] = a1; dst[2] = a2; dst[3] = a3;
        } else if (wl < 28) {
            int kq = wl - 24;
            int m0 = r*128 + lane*4;
            int k0 = kq << 6;
            float a0 = 0.f, a1 = 0.f, a2 = 0.f, a3 = 0.f;
            #pragma unroll 8
            for (int k = k0; k < k0 + 64; k++) {
                float4 w = *(const float4*)(g_WqT + k*256 + m0);
                float hk = s_h[k];
                a0 += w.x*hk; a1 += w.y*hk; a2 += w.z*hk; a3 += w.w*hk;
            }
            float* dst = s_qp + kq*128 + lane*4;
            dst[0] = a0; dst[1] = a1; dst[2] = a2; dst[3] = a3;
        } else {
            int kq = wl - 28;
            if (lane < 24) {
                int c0 = r*96 + lane*4;
                int k0 = kq << 6;
                float a0 = 0.f, a1 = 0.f, a2 = 0.f, a3 = 0.f;
                #pragma unroll 8
                for (int k = k0; k < k0 + 64; k++) {
                    float4 w = *(const float4*)(g_WchT + k*192 + c0);
                    float hk = s_h[k];
                    a0 += w.x*hk; a1 += w.y*hk; a2 += w.z*hk; a3 += w.w*hk;
                }
                float* dst = s_cp + kq*96 + lane*4;
                dst[0] = a0; dst[1] = a1; dst[2] = a2; dst[3] = a3;
            }
        }
        __syncthreads();

        // ===== S2: combines (+DSMEM exchange), gi load, beta, head(t-1) =====
        if (tid < 128) {
            float v = s_qp[tid] + s_qp[128 + tid] + s_qp[256 + tid] + s_qp[384 + tid]
                    + s_bq[tid];
            s_q[r*128 + tid] = v;
            p_q[r*128 + tid] = v;
        } else if (tid < 224) {
            int j = tid - 128;
            float v = s_cp[j] + s_cp[96 + j] + s_cp[192 + j] + s_cp[288 + j]
                    + g_cxA[(t*32 + b)*192 + r*96 + j];
            v = fmaxf(v, 0.f);
            s_cand[t*192 + r*96 + j] = v;
            p_cand[t*192 + r*96 + j] = v;
        } else if (tid < 608) {
            int j = tid - 224;
            int g = j >> 7, jj = j & 127;
            s_gi[j] = g_giA[(t*32 + b)*768 + g*256 + r*128 + jj];
        } else if (wl == 20) {
            const float4* u4 = (const float4*)s_u;
            float acc = dot8(u4[lane], u4[32 + lane], h4[lane], h4[32 + lane]);
            acc = warp_sum(acc);
            if (lane == 0) {
                float sp = (acc > 0.f) ? acc + log1pf(expf(-acc)) : log1pf(expf(acc));
                s_beta[0] = sp + 1.f;
            }
        } else if (wl == 21 && rank == 0 && t > 0) {
            float logit[10];
            float mx = -1e30f;
            #pragma unroll
            for (int o = 0; o < 10; o++) {
                float s = 0.f;
                #pragma unroll
                for (int j = 0; j < 8; j++) {
                    int k = lane + 32*j;
                    s += s_Wout[o*H_ + k] * s_h[k];
                }
                s = warp_sum(s);
                s += s_bo[o];
                logit[o] = s;
                mx = fmaxf(mx, s);
            }
            float se = 0.f;
            #pragma unroll
            for (int o = 0; o < 10; o++) se += expf(logit[o] - mx);
            float lse = mx + logf(se);
            if (lane == 0) {
                #pragma unroll
                for (int o = 0; o < 10; o++)
                    out[HSOFF + ((t-1)*10 + o)*B_ + b] = logit[o] - lse;
            }
        }
        __syncthreads();
        cl.sync();                                // q + cand halves visible

        // ===== S3: d_s (replicated, warp per s < t) =====
        if (wl < t) {
            float acc = 0.f;
            #pragma unroll
            for (int j = 0; j < 6; j++) {
                int c = lane + 32*j;
                acc += s_cand[wl*192 + c] * s_q[A_ + c];
            }
            acc = warp_sum(acc);
            if (lane == 0) s_d[wl] = acc;
        }
        __syncthreads();

        // ===== S4: sim (thread per n) + block softmax -> w (replicated) =====
        {
            int n = tid;
            float acc = 0.f;
            #pragma unroll 8
            for (int a = 0; a < A_; a++)
                acc += s_q[a] * g_addrT[a*N_ + n];
            for (int s = 0; s < t; s++)
                acc += s_w[s*N_ + n] * s_d[s];
            float v = s_beta[0] * acc;
            float mx = warp_max(v);
            if (lane == 0) s_mx[wl] = mx;
            __syncthreads();
            float mb = s_mx[0];
            #pragma unroll
            for (int w = 1; w < 32; w++) mb = fmaxf(mb, s_mx[w]);
            float e = expf(v - mb);
            float es = warp_sum(e);
            if (lane == 0) s_e[wl] = es;
            __syncthreads();
            float ss = 0.f;
            #pragma unroll
            for (int w = 0; w < 32; w++) ss += s_e[w];
            s_w[t*N_ + n] = e / ss;
        }
        __syncthreads();

        // ===== S5: G_s (warps < t) + ra (all warps) — replicated =====
        if (wl < t) {
            const float4* wsp = (const float4*)(s_w + wl*N_);
            const float4* wtp = (const float4*)(s_w + t*N_);
            float g = 0.f;
            #pragma unroll
            for (int j = 0; j < 8; j++) {
                float4 a_ = wsp[j*32 + lane];
                float4 c_ = wtp[j*32 + lane];
                g += a_.x*c_.x + a_.y*c_.y + a_.z*c_.z + a_.w*c_.w;
            }
            g = warp_sum(g);
            if (lane == 0) s_G[wl] = g;
        }
        {
            const float4* at4 = (const float4*)g_addrT;
            const float4* wtp = (const float4*)(s_w + t*N_);
            float a0 = 0.f, a1 = 0.f;
            #pragma unroll
            for (int j = 0; j < 8; j++) {
                float4 wv = wtp[j*32 + lane];
                float4 r0 = at4[wl*256 + j*32 + lane];
                float4 r1 = at4[(wl + 32)*256 + j*32 + lane];
                a0 += wv.x*r0.x + wv.y*r0.y + wv.z*r0.z + wv.w*r0.w;
                a1 += wv.x*r1.x + wv.y*r1.y + wv.z*r1.z + wv.w*r1.w;
            }
            a0 = warp_sum(a0);
            a1 = warp_sum(a1);
            if (lane == 0) { s_r[wl] = a0; s_r[wl + 32] = a1; }
        }
        __syncthreads();

        // ===== S6: rc[c] (replicated) =====
        if (tid < C_) {
            float acc = 0.f;
            for (int s = 0; s < t; s++)
                acc += s_G[s] * s_cand[s*192 + tid];
            s_r[A_ + tid] = acc;
        }
        __syncthreads();

        // ===== S7: gm partials (24 warps, r's row half) =====
        if (wl < 24) {
            int g = wl >> 3, kq = wl & 7;
            int row = g*256 + r*128 + lane*4;
            int m0 = kq << 5;
            float a0 = 0.f, a1 = 0.f, a2 = 0.f, a3 = 0.f;
            #pragma unroll 8
            for (int m = m0; m < m0 + 32; m++) {
                float4 w = *(const float4*)(g_WmT + m*768 + row);
                float rm = s_r[m];
                a0 += w.x*rm; a1 += w.y*rm; a2 += w.z*rm; a3 += w.w*rm;
            }
            float* dst = s_gmp + kq*384 + g*128 + lane*4;
            dst[0] = a0; dst[1] = a1; dst[2] = a2; dst[3] = a3;
        }
        __syncthreads();

        // ===== S8: gate combine + h update (local half) + exchange =====
        if (tid < 128) {
            int hid = r*128 + tid;
            float gh0 = s_bh[tid],       gm0 = s_bm[tid];
            float gh1 = s_bh[128 + tid], gm1 = s_bm[128 + tid];
            float gh2 = s_bh[256 + tid], gm2 = s_bm[256 + tid];
            #pragma unroll
            for (int kq = 0; kq < 8; kq++) {
                gh0 += s_ghp[kq*384 + tid];
                gh1 += s_ghp[kq*384 + 128 + tid];
                gh2 += s_ghp[kq*384 + 256 + tid];
                gm0 += s_gmp[kq*384 + tid];
                gm1 += s_gmp[kq*384 + 128 + tid];
                gm2 += s_gmp[kq*384 + 256 + tid];
            }
            float rr = 1.f / (1.f + expf(-(s_gi[tid] + gh0 + gm0)));
            float zz = 1.f / (1.f + expf(-(s_gi[128 + tid] + gh1 + gm1)));
            float nn = tanhf(s_gi[256 + tid] + gm2 + rr*gh2);
            float hn = (1.f - zz)*nn + zz*s_h[hid];
            s_h[hid] = hn;
            p_h[hid] = hn;
            out[t*H_*B_ + hid*32 + b] = hn;
        }
        __syncthreads();
        cl.sync();                                // h halves visible
    }

    // final head (t = T-1), rank 0
    if (rank == 0 && wl == 0) {
        float logit[10];
        float mx = -1e30f;
        #pragma unroll
        for (int o = 0; o < 10; o++) {
            float s = 0.f;
            #pragma unroll
            for (int j = 0; j < 8; j++) {
                int k = lane + 32*j;
                s += s_Wout[o*H_ + k] * s_h[k];
            }
            s = warp_sum(s);
            s += s_bo[o];
            logit[o] = s;
            mx = fmaxf(mx, s);
        }
        float se = 0.f;
        #pragma unroll
        for (int o = 0; o < 10; o++) se += expf(logit[o] - mx);
        float lse = mx + logf(se);
        if (lane == 0) {
            #pragma unroll
            for (int o = 0; o < 10; o++)
                out[HSOFF + ((T_-1)*10 + o)*B_ + b] = logit[o] - lse;
        }
    }
}

extern "C" void kernel_launch(void* const* d_in, const int* in_sizes, int n_in,
                              void* d_out, int out_size) {
    (void)in_sizes; (void)n_in; (void)out_size;
    const float* batch = (const float*)d_in[0];
    const float* Wi    = (const float*)d_in[1];
    const float* bi    = (const float*)d_in[2];
    const float* Wh    = (const float*)d_in[3];
    const float* bh    = (const float*)d_in[4];
    const float* Wm    = (const float*)d_in[5];
    const float* bm    = (const float*)d_in[6];
    const float* Wout  = (const float*)d_in[7];
    const float* bo    = (const float*)d_in[8];
    const float* addr  = (const float*)d_in[9];
    const float* Wq    = (const float*)d_in[10];
    const float* bq    = (const float*)d_in[11];
    const float* u     = (const float*)d_in[12];
    const float* Wch   = (const float*)d_in[13];
    const float* Wci   = (const float*)d_in[14];
    float* out = (float*)d_out;

    static int smem_set = 0;
    if (!smem_set) {
        cudaFuncSetAttribute((const void*)k_run,
                             cudaFuncAttributeMaxDynamicSharedMemorySize,
                             SMEM_FLOATS * 4);
        smem_set = 1;
    }
    k_init<<<1536, 256>>>(batch, addr, Wi, bi, Wci, Wh, Wq, Wch, Wm);
    k_run<<<64, 1024, SMEM_FLOATS * 4>>>(bh, bq, u, bm, Wout, bo, out);
}

// round 14
// speedup vs baseline: 3.0673x; 1.4233x over previous
#include <cuda_runtime.h>
#include <cooperative_groups.h>
#include <math.h>

namespace cg = cooperative_groups;

#define B_ 32
#define T_ 32
#define F_ 64
#define H_ 256
#define N_ 1024
#define A_ 64
#define C_ 192
#define M_ 256
#define HSOFF (T_*H_*B_)

// ---------------- precomputed globals ----------------
__device__ __align__(16) float g_addrT[A_*N_];     // addrT[a*1024+n]
__device__ __align__(16) float g_giA[T_*B_*768];   // gi: [(t*32+b)*768+row]
__device__ __align__(16) float g_cxA[T_*B_*C_];    // Wci@x: [(t*32+b)*192+c]
__device__ __align__(16) float g_WhT[H_*768];      // [k*768+row]
__device__ __align__(16) float g_WqT[H_*M_];       // [k*256+m]
__device__ __align__(16) float g_WchT[H_*C_];      // [k*192+c]
__device__ __align__(16) float g_WmT[M_*768];      // [m*768+row]

__device__ __forceinline__ float warp_sum(float v) {
    #pragma unroll
    for (int o = 16; o; o >>= 1) v += __shfl_xor_sync(0xffffffffu, v, o);
    return v;
}
__device__ __forceinline__ float warp_max(float v) {
    #pragma unroll
    for (int o = 16; o; o >>= 1) v = fmaxf(v, __shfl_xor_sync(0xffffffffu, v, o));
    return v;
}
__device__ __forceinline__ float dot8(float4 w1, float4 w2, float4 h1, float4 h2) {
    return w1.x*h1.x + w1.y*h1.y + w1.z*h1.z + w1.w*h1.w
         + w2.x*h2.x + w2.y*h2.y + w2.z*h2.z + w2.w*h2.w;
}

// ================= K0: init (once) =================
__global__ __launch_bounds__(256, 4)
void k_init(const float* __restrict__ batch, const float* __restrict__ addr,
            const float* __restrict__ Wi, const float* __restrict__ bi,
            const float* __restrict__ Wci, const float* __restrict__ Wh,
            const float* __restrict__ Wq, const float* __restrict__ Wch,
            const float* __restrict__ Wm)
{
    int blk = blockIdx.x, tid = threadIdx.x, lane = tid & 31, wl = tid >> 5;
    if (blk < 1024) {
        int t = blk >> 5, b = blk & 31;
        __shared__ float sx[64];
        if (tid < 64) {
            int idx = tid*32 + b;          // raw-reshape: x_t[f,b] = flat[f*32+b]
            sx[tid] = batch[(idx >> 6)*(T_*F_) + t*F_ + (idx & 63)];
        }
        __syncthreads();
        for (int r = wl; r < 960; r += 8) {
            if (r < 768) {
                float acc = Wi[r*64 + lane]*sx[lane] + Wi[r*64 + 32 + lane]*sx[32 + lane];
                acc = warp_sum(acc);
                if (lane == 0) g_giA[(t*32 + b)*768 + r] = acc + bi[r];
            } else {
                int c = r - 768;
                float acc = Wci[c*64 + lane]*sx[lane] + Wci[c*64 + 32 + lane]*sx[32 + lane];
                acc = warp_sum(acc);
                if (lane == 0) g_cxA[(t*32 + b)*192 + c] = acc;
            }
        }
    } else {
        int i0 = (blk - 1024)*256 + tid;
        int STR = (gridDim.x - 1024)*256;
        for (int i = i0; i < A_*N_; i += STR)
            g_addrT[i] = addr[(i & 1023)*A_ + (i >> 10)];
        for (int i = i0; i < H_*768; i += STR)
            g_WhT[i] = Wh[(i % 768)*H_ + (i / 768)];
        for (int i = i0; i < H_*M_; i += STR)
            g_WqT[i] = Wq[(i & 255)*H_ + (i >> 8)];
        for (int i = i0; i < H_*C_; i += STR)
            g_WchT[i] = Wch[(i % 192)*H_ + (i / 192)];
        for (int i = i0; i < M_*768; i += STR)
            g_WmT[i] = Wm[(i % 768)*H_ + (i / 768)];
    }
}

// ================= smem layout (floats) =================
#define SM_W     0          // 32768  whist[32][1024] (full, via w-quarter bcast)
#define SM_CAND  32768      // 6144   cand[32][192]   (full via exchange)
#define SM_GI    38912      // 192    gi slice [g*64+j]
#define SM_GHP   39104      // 1536   gh partials (8 kq x 192)
#define SM_GMP   40640      // 1536   gm partials
#define SM_QP    42176      // 256    q partials (4 kq x 64)
#define SM_CP    42432      // 192    cand partials (4 kq x 48)
#define SM_Q     42624      // 256    full q (exchange)
#define SM_H     42880      // 256    full h (exchange)
#define SM_R     43136      // 256    reading
#define SM_GP    43392      // 128    G partials (4 ranks x 32)
#define SM_RAP   43520      // 256    ra partials (4 ranks x 64)
#define SM_STAT  43776      // 8      softmax (m,s) per rank
#define SM_BH    43784      // 192
#define SM_BM    43976      // 192
#define SM_BQ    44168      // 64
#define SM_U     44232      // 256
#define SM_WOUT  44488      // 2560
#define SM_BO    47048      // 16
#define SM_D     47064      // 32
#define SM_G     47096      // 32
#define SM_MX    47128      // 8
#define SM_E     47136      // 8
#define SM_BETA  47144      // 4
#define SMEM_FLOATS 47152

__global__ __launch_bounds__(1024, 1) __cluster_dims__(4, 1, 1)
void k_run(const float* __restrict__ bh,  const float* __restrict__ bq,
           const float* __restrict__ uvec,const float* __restrict__ bm,
           const float* __restrict__ Wout,const float* __restrict__ bo,
           float* __restrict__ out)
{
    extern __shared__ __align__(16) float sm[];
    float* s_w    = sm + SM_W;
    float* s_cand = sm + SM_CAND;
    float* s_gi   = sm + SM_GI;
    float* s_ghp  = sm + SM_GHP;
    float* s_gmp  = sm + SM_GMP;
    float* s_qp   = sm + SM_QP;
    float* s_cp   = sm + SM_CP;
    float* s_q    = sm + SM_Q;
    float* s_h    = sm + SM_H;
    float* s_r    = sm + SM_R;
    float* s_Gp   = sm + SM_GP;
    float* s_rap  = sm + SM_RAP;
    float* s_stat = sm + SM_STAT;
    float* s_bh   = sm + SM_BH;
    float* s_bm   = sm + SM_BM;
    float* s_bq   = sm + SM_BQ;
    float* s_u    = sm + SM_U;
    float* s_Wout = sm + SM_WOUT;
    float* s_bo   = sm + SM_BO;
    float* s_d    = sm + SM_D;
    float* s_G    = sm + SM_G;
    float* s_mx   = sm + SM_MX;
    float* s_e    = sm + SM_E;
    float* s_beta = sm + SM_BETA;

    cg::cluster_group cl = cg::this_cluster();
    const unsigned rank = cl.block_rank();
    float* peer[3];
    #pragma unroll
    for (int i = 0; i < 3; i++)
        peer[i] = (float*)cl.map_shared_rank((void*)sm, (rank + 1 + i) & 3);

    const int b = blockIdx.x >> 2;
    const int r = (int)rank;
    const int tid = threadIdx.x, lane = tid & 31, wl = tid >> 5;
    const float4* h4 = (const float4*)s_h;

    // ---- one-time staging ----
    if (tid < 192) {
        int g = tid >> 6, j = tid & 63;
        s_bh[tid] = bh[g*256 + r*64 + j];
        s_bm[tid] = bm[g*256 + r*64 + j];
    }
    if (tid < 64) s_bq[tid] = bq[r*64 + tid];
    if (tid < 256) { s_u[tid] = uvec[tid]; s_h[tid] = 0.f; }
    for (int i = tid; i < 2560; i += 1024) s_Wout[i] = Wout[i];
    if (tid < 10) s_bo[tid] = bo[tid];
    cl.sync();

    for (int t = 0; t < T_; t++) {
        // ===== S1: gh(24w) + q(4w) + cand(4w) partials — r's row quarters =====
        if (wl < 24) {
            int g = wl >> 3, kq = wl & 7;
            int row = g*256 + r*64 + lane*2;
            int k0 = kq << 5;
            float a0 = 0.f, a1 = 0.f;
            #pragma unroll 8
            for (int k = k0; k < k0 + 32; k++) {
                float2 w = *(const float2*)(g_WhT + k*768 + row);
                float hk = s_h[k];
                a0 += w.x*hk; a1 += w.y*hk;
            }
            s_ghp[kq*192 + g*64 + lane*2    ] = a0;
            s_ghp[kq*192 + g*64 + lane*2 + 1] = a1;
        } else if (wl < 28) {
            int kq = wl - 24, k0 = kq << 6;
            int m0 = r*64 + lane*2;
            float a0 = 0.f, a1 = 0.f;
            #pragma unroll 8
            for (int k = k0; k < k0 + 64; k++) {
                float2 w = *(const float2*)(g_WqT + k*256 + m0);
                float hk = s_h[k];
                a0 += w.x*hk; a1 += w.y*hk;
            }
            s_qp[kq*64 + lane*2    ] = a0;
            s_qp[kq*64 + lane*2 + 1] = a1;
        } else {
            int kq = wl - 28, k0 = kq << 6;
            if (lane < 24) {
                int c0 = r*48 + lane*2;
                float a0 = 0.f, a1 = 0.f;
                #pragma unroll 8
                for (int k = k0; k < k0 + 64; k++) {
                    float2 w = *(const float2*)(g_WchT + k*192 + c0);
                    float hk = s_h[k];
                    a0 += w.x*hk; a1 += w.y*hk;
                }
                s_cp[kq*48 + lane*2    ] = a0;
                s_cp[kq*48 + lane*2 + 1] = a1;
            }
        }
        __syncthreads();

        // ===== S2: combines + broadcasts, gi load, beta, head(t-1) =====
        if (tid < 64) {
            float v = s_qp[tid] + s_qp[64 + tid] + s_qp[128 + tid] + s_qp[192 + tid]
                    + s_bq[tid];
            int off = SM_Q + r*64 + tid;
            s_q[r*64 + tid] = v;
            peer[0][off] = v; peer[1][off] = v; peer[2][off] = v;
        } else if (tid < 112) {
            int j = tid - 64;
            float v = s_cp[j] + s_cp[48 + j] + s_cp[96 + j] + s_cp[144 + j]
                    + g_cxA[(t*32 + b)*192 + r*48 + j];
            v = fmaxf(v, 0.f);
            int off = SM_CAND + t*192 + r*48 + j;
            s_cand[t*192 + r*48 + j] = v;
            peer[0][off] = v; peer[1][off] = v; peer[2][off] = v;
        } else if (tid >= 128 && tid < 320) {
            int j = tid - 128;
            int g = j >> 6, jj = j & 63;
            s_gi[j] = g_giA[(t*32 + b)*768 + g*256 + r*64 + jj];
        } else if (wl == 12 && rank == 0) {
            const float4* u4 = (const float4*)s_u;
            float acc = dot8(u4[lane], u4[32 + lane], h4[lane], h4[32 + lane]);
            acc = warp_sum(acc);
            if (lane == 0) {
                float sp = (acc > 0.f) ? acc + log1pf(expf(-acc)) : log1pf(expf(acc));
                float bv = sp + 1.f;
                s_beta[0] = bv;
                peer[0][SM_BETA] = bv; peer[1][SM_BETA] = bv; peer[2][SM_BETA] = bv;
            }
        } else if (wl == 13 && rank == 0 && t > 0) {
            float logit[10];
            float mx = -1e30f;
            #pragma unroll
            for (int o = 0; o < 10; o++) {
                float s = 0.f;
                #pragma unroll
                for (int j = 0; j < 8; j++) {
                    int k = lane + 32*j;
                    s += s_Wout[o*H_ + k] * s_h[k];
                }
                s = warp_sum(s);
                s += s_bo[o];
                logit[o] = s;
                mx = fmaxf(mx, s);
            }
            float se = 0.f;
            #pragma unroll
            for (int o = 0; o < 10; o++) se += expf(logit[o] - mx);
            float lse = mx + logf(se);
            if (lane == 0) {
                #pragma unroll
                for (int o = 0; o < 10; o++)
                    out[HSOFF + ((t-1)*10 + o)*B_ + b] = logit[o] - lse;
            }
        }
        cl.sync();                              // q, cand, beta visible everywhere

        // ===== S3: d_s (replicated, warp per s < t) =====
        if (wl < t) {
            float acc = 0.f;
            #pragma unroll
            for (int j = 0; j < 6; j++) {
                int c = lane + 32*j;
                acc += s_cand[wl*192 + c] * s_q[A_ + c];
            }
            acc = warp_sum(acc);
            if (lane == 0) s_d[wl] = acc;
        }
        __syncthreads();

        // ===== S4: sim over n-quarter + cluster softmax =====
        float e_reg = 0.f, mloc = 0.f, v = 0.f;
        if (tid < 256) {
            int n = r*256 + tid;
            float acc = 0.f;
            #pragma unroll 8
            for (int a = 0; a < A_; a++)
                acc += s_q[a] * g_addrT[a*N_ + n];
            for (int s = 0; s < t; s++)
                acc += s_w[s*N_ + n] * s_d[s];
            v = s_beta[0] * acc;
            float mx = warp_max(v);
            if (lane == 0) s_mx[wl] = mx;
        }
        __syncthreads();
        if (tid < 256) {
            mloc = s_mx[0];
            #pragma unroll
            for (int w = 1; w < 8; w++) mloc = fmaxf(mloc, s_mx[w]);
            e_reg = expf(v - mloc);
            float es = warp_sum(e_reg);
            if (lane == 0) s_e[wl] = es;
        }
        __syncthreads();
        if (tid == 0) {
            float sl = 0.f;
            #pragma unroll
            for (int w = 0; w < 8; w++) sl += s_e[w];
            s_stat[r*2] = mloc; s_stat[r*2 + 1] = sl;
            #pragma unroll
            for (int i = 0; i < 3; i++) {
                peer[i][SM_STAT + r*2] = mloc;
                peer[i][SM_STAT + r*2 + 1] = sl;
            }
        }
        cl.sync();                              // stats visible
        if (tid < 256) {
            float M = fmaxf(fmaxf(s_stat[0], s_stat[2]), fmaxf(s_stat[4], s_stat[6]));
            float S = s_stat[1]*expf(s_stat[0] - M) + s_stat[3]*expf(s_stat[2] - M)
                    + s_stat[5]*expf(s_stat[4] - M) + s_stat[7]*expf(s_stat[6] - M);
            float wv = e_reg * expf(mloc - M) / S;
            int off = SM_W + t*N_ + r*256 + tid;
            s_w[t*N_ + r*256 + tid] = wv;
            peer[0][off] = wv; peer[1][off] = wv; peer[2][off] = wv;
        }
        cl.sync();                              // full w_t visible

        // ===== S5: G partials (warps<t) + ra partials (all warps), n-quarter =====
        if (wl < t) {
            const float4* wsp = (const float4*)(s_w + wl*N_ + r*256);
            const float4* wtp = (const float4*)(s_w + t*N_ + r*256);
            float4 a0 = wsp[lane], c0 = wtp[lane];
            float4 a1 = wsp[32 + lane], c1 = wtp[32 + lane];
            float g = a0.x*c0.x + a0.y*c0.y + a0.z*c0.z + a0.w*c0.w
                    + a1.x*c1.x + a1.y*c1.y + a1.z*c1.z + a1.w*c1.w;
            g = warp_sum(g);
            if (lane == 0) {
                int off = SM_GP + r*32 + wl;
                s_Gp[r*32 + wl] = g;
                peer[0][off] = g; peer[1][off] = g; peer[2][off] = g;
            }
        }
        {
            const float4* wtp = (const float4*)(s_w + t*N_ + r*256);
            const float4* at0 = (const float4*)(g_addrT + wl*N_ + r*256);
            const float4* at1 = (const float4*)(g_addrT + (wl + 32)*N_ + r*256);
            float4 w0 = wtp[lane], w1 = wtp[32 + lane];
            float4 x0 = at0[lane], x1 = at0[32 + lane];
            float4 y0 = at1[lane], y1 = at1[32 + lane];
            float a0 = w0.x*x0.x + w0.y*x0.y + w0.z*x0.z + w0.w*x0.w
                     + w1.x*x1.x + w1.y*x1.y + w1.z*x1.z + w1.w*x1.w;
            float a1 = w0.x*y0.x + w0.y*y0.y + w0.z*y0.z + w0.w*y0.w
                     + w1.x*y1.x + w1.y*y1.y + w1.z*y1.z + w1.w*y1.w;
            a0 = warp_sum(a0);
            a1 = warp_sum(a1);
            if (lane == 0) {
                int off0 = SM_RAP + r*64 + wl;
                int off1 = SM_RAP + r*64 + wl + 32;
                s_rap[r*64 + wl] = a0;
                s_rap[r*64 + wl + 32] = a1;
                peer[0][off0] = a0; peer[1][off0] = a0; peer[2][off0] = a0;
                peer[0][off1] = a1; peer[1][off1] = a1; peer[2][off1] = a1;
            }
        }
        cl.sync();                              // G/ra partials visible

        // ===== S6: combine G + ra, then rc =====
        if (tid < 32) {
            s_G[tid] = s_Gp[tid] + s_Gp[32 + tid] + s_Gp[64 + tid] + s_Gp[96 + tid];
        } else if (tid < 96) {
            int a = tid - 32;
            s_r[a] = s_rap[a] + s_rap[64 + a] + s_rap[128 + a] + s_rap[192 + a];
        }
        __syncthreads();
        if (tid < 192) {
            float acc = 0.f;
            for (int s = 0; s < t; s++)
                acc += s_G[s] * s_cand[s*192 + tid];
            s_r[A_ + tid] = acc;
        }
        __syncthreads();

        // ===== S7: gm partials (24 warps, r's row quarter) =====
        if (wl < 24) {
            int g = wl >> 3, kq = wl & 7;
            int row = g*256 + r*64 + lane*2;
            int m0 = kq << 5;
            float a0 = 0.f, a1 = 0.f;
            #pragma unroll 8
            for (int m = m0; m < m0 + 32; m++) {
                float2 w = *(const float2*)(g_WmT + m*768 + row);
                float rm = s_r[m];
                a0 += w.x*rm; a1 += w.y*rm;
            }
            s_gmp[kq*192 + g*64 + lane*2    ] = a0;
            s_gmp[kq*192 + g*64 + lane*2 + 1] = a1;
        }
        __syncthreads();

        // ===== S8: gate combine + h slice update + broadcast =====
        if (tid < 64) {
            int hid = r*64 + tid;
            float gh0 = s_bh[tid],       gm0 = s_bm[tid];
            float gh1 = s_bh[64 + tid],  gm1 = s_bm[64 + tid];
            float gh2 = s_bh[128 + tid], gm2 = s_bm[128 + tid];
            #pragma unroll
            for (int kq = 0; kq < 8; kq++) {
                gh0 += s_ghp[kq*192 + tid];
                gh1 += s_ghp[kq*192 + 64 + tid];
                gh2 += s_ghp[kq*192 + 128 + tid];
                gm0 += s_gmp[kq*192 + tid];
                gm1 += s_gmp[kq*192 + 64 + tid];
                gm2 += s_gmp[kq*192 + 128 + tid];
            }
            float rr = 1.f / (1.f + expf(-(s_gi[tid] + gh0 + gm0)));
            float zz = 1.f / (1.f + expf(-(s_gi[64 + tid] + gh1 + gm1)));
            float nn = tanhf(s_gi[128 + tid] + gm2 + rr*gh2);
            float hn = (1.f - zz)*nn + zz*s_h[hid];
            int off = SM_H + hid;
            s_h[hid] = hn;
            peer[0][off] = hn; peer[1][off] = hn; peer[2][off] = hn;
            out[t*H_*B_ + hid*32 + b] = hn;
        }
        cl.sync();                              // full h visible
    }

    // final head (t = T-1), rank 0
    if (rank == 0 && wl == 0) {
        float logit[10];
        float mx = -1e30f;
        #pragma unroll
        for (int o = 0; o < 10; o++) {
            float s = 0.f;
            #pragma unroll
            for (int j = 0; j < 8; j++) {
                int k = lane + 32*j;
                s += s_Wout[o*H_ + k] * s_h[k];
            }
            s = warp_sum(s);
            s += s_bo[o];
            logit[o] = s;
            mx = fmaxf(mx, s);
        }
        float se = 0.f;
        #pragma unroll
        for (int o = 0; o < 10; o++) se += expf(logit[o] - mx);
        float lse = mx + logf(se);
        if (lane == 0) {
            #pragma unroll
            for (int o = 0; o < 10; o++)
                out[HSOFF + ((T_-1)*10 + o)*B_ + b] = logit[o] - lse;
        }
    }
}

extern "C" void kernel_launch(void* const* d_in, const int* in_sizes, int n_in,
                              void* d_out, int out_size) {
    (void)in_sizes; (void)n_in; (void)out_size;
    const float* batch = (const float*)d_in[0];
    const float* Wi    = (const float*)d_in[1];
    const float* bi    = (const float*)d_in[2];
    const float* Wh    = (const float*)d_in[3];
    const float* bh    = (const float*)d_in[4];
    const float* Wm    = (const float*)d_in[5];
    const float* bm    = (const float*)d_in[6];
    const float* Wout  = (const float*)d_in[7];
    const float* bo    = (const float*)d_in[8];
    const float* addr  = (const float*)d_in[9];
    const float* Wq    = (const float*)d_in[10];
    const float* bq    = (const float*)d_in[11];
    const float* u     = (const float*)d_in[12];
    const float* Wch   = (const float*)d_in[13];
    const float* Wci   = (const float*)d_in[14];
    float* out = (float*)d_out;

    static int smem_set = 0;
    if (!smem_set) {
        cudaFuncSetAttribute((const void*)k_run,
                             cudaFuncAttributeMaxDynamicSharedMemorySize,
                             SMEM_FLOATS * 4);
        smem_set = 1;
    }
    k_init<<<1536, 256>>>(batch, addr, Wi, bi, Wci, Wh, Wq, Wch, Wm);
    k_run<<<128, 1024, SMEM_FLOATS * 4>>>(bh, bq, u, bm, Wout, bo, out);
}

// round 15
// speedup vs baseline: 3.5279x; 1.1502x over previous
#include <cuda_runtime.h>
#include <cooperative_groups.h>
#include <math.h>

namespace cg = cooperative_groups;

#define B_ 32
#define T_ 32
#define F_ 64
#define H_ 256
#define N_ 1024
#define A_ 64
#define C_ 192
#define M_ 256
#define HSOFF (T_*H_*B_)

// ---------------- precomputed globals ----------------
__device__ __align__(16) float g_addrT[A_*N_];     // addrT[a*1024+n]
__device__ __align__(16) float g_giA[T_*B_*768];   // gi: [(t*32+b)*768+row]
__device__ __align__(16) float g_cxA[T_*B_*C_];    // Wci@x: [(t*32+b)*192+c]
__device__ __align__(16) float g_WhT[H_*768];      // [k*768+row]
__device__ __align__(16) float g_WqT[H_*M_];       // [k*256+m]
__device__ __align__(16) float g_WchT[H_*C_];      // [k*192+c]
__device__ __align__(16) float g_WmT[M_*768];      // [m*768+row]

__device__ __forceinline__ float warp_sum(float v) {
    #pragma unroll
    for (int o = 16; o; o >>= 1) v += __shfl_xor_sync(0xffffffffu, v, o);
    return v;
}
__device__ __forceinline__ float warp_max(float v) {
    #pragma unroll
    for (int o = 16; o; o >>= 1) v = fmaxf(v, __shfl_xor_sync(0xffffffffu, v, o));
    return v;
}
__device__ __forceinline__ float dot8(float4 w1, float4 w2, float4 h1, float4 h2) {
    return w1.x*h1.x + w1.y*h1.y + w1.z*h1.z + w1.w*h1.w
         + w2.x*h2.x + w2.y*h2.y + w2.z*h2.z + w2.w*h2.w;
}

// ================= K_tr: tiled transposes (once) =================
__global__ __launch_bounds__(256, 4)
void k_tr(const float* __restrict__ Wh, const float* __restrict__ Wq,
          const float* __restrict__ Wch, const float* __restrict__ Wm,
          const float* __restrict__ addr)
{
    __shared__ float tile[32][33];
    int blk = blockIdx.x, tid = threadIdx.x;
    const float* src; float* dst; int R, C, tr, tc;
    if (blk < 192)      { src = Wh;  dst = g_WhT;  R = 768;  C = 256; int i = blk;       tr = i >> 3; tc = i & 7; }
    else if (blk < 384) { src = Wm;  dst = g_WmT;  R = 768;  C = 256; int i = blk - 192; tr = i >> 3; tc = i & 7; }
    else if (blk < 448) { src = Wq;  dst = g_WqT;  R = 256;  C = 256; int i = blk - 384; tr = i >> 3; tc = i & 7; }
    else if (blk < 496) { src = Wch; dst = g_WchT; R = 192;  C = 256; int i = blk - 448; tr = i >> 3; tc = i & 7; }
    else                { src = addr;dst = g_addrT;R = 1024; C = 64;  int i = blk - 496; tr = i >> 1; tc = i & 1; }
    int r0 = tr*32, c0 = tc*32, rr = tid >> 5, cc = tid & 31;
    #pragma unroll
    for (int p = 0; p < 4; p++)
        tile[rr + p*8][cc] = src[(r0 + rr + p*8)*C + c0 + cc];
    __syncthreads();
    #pragma unroll
    for (int p = 0; p < 4; p++)
        dst[(c0 + rr + p*8)*R + r0 + cc] = tile[cc][rr + p*8];
}

// ================= K0: gi / cx precompute (once) =================
__global__ __launch_bounds__(256, 4)
void k_init(const float* __restrict__ batch,
            const float* __restrict__ Wi, const float* __restrict__ bi,
            const float* __restrict__ Wci)
{
    int blk = blockIdx.x, tid = threadIdx.x, lane = tid & 31, wl = tid >> 5;
    int t = blk >> 5, b = blk & 31;
    __shared__ float sx[64];
    if (tid < 64) {
        int idx = tid*32 + b;          // raw-reshape: x_t[f,b] = flat[f*32+b]
        sx[tid] = batch[(idx >> 6)*(T_*F_) + t*F_ + (idx & 63)];
    }
    __syncthreads();
    for (int r = wl; r < 960; r += 8) {
        if (r < 768) {
            float acc = Wi[r*64 + lane]*sx[lane] + Wi[r*64 + 32 + lane]*sx[32 + lane];
            acc = warp_sum(acc);
            if (lane == 0) g_giA[(t*32 + b)*768 + r] = acc + bi[r];
        } else {
            int c = r - 768;
            float acc = Wci[c*64 + lane]*sx[lane] + Wci[c*64 + 32 + lane]*sx[32 + lane];
            acc = warp_sum(acc);
            if (lane == 0) g_cxA[(t*32 + b)*192 + c] = acc;
        }
    }
}

// ================= smem layout (floats) =================
#define SM_W     0          // 8192   whist[32][256]  (own n-quarter only)
#define SM_ADDR  8192       // 16384  addrT quarter [a*256+nl]
#define SM_CAND  24576      // 6144   cand[32][192] (full via exchange)
#define SM_GI    30720      // 192
#define SM_GHP   30912      // 1536
#define SM_GMP   32448      // 1536
#define SM_QP    33984      // 256
#define SM_CP    34240      // 192
#define SM_Q     34432      // 256
#define SM_H     34688      // 256
#define SM_R     34944      // 256
#define SM_SIMP  35200      // 1024   sim partials (4 grp x 256)
#define SM_GP    36224      // 128
#define SM_RAP   36352      // 256
#define SM_STAT  36608      // 8
#define SM_BH    36616      // 192
#define SM_BM    36808      // 192
#define SM_BQ    37000      // 64
#define SM_U     37064      // 256
#define SM_WOUT  37320      // 2560
#define SM_BO    39880      // 16
#define SM_D     39896      // 32
#define SM_G     39928      // 32
#define SM_MX    39960      // 8
#define SM_E     39968      // 8
#define SM_BETA  39976      // 4
#define SMEM_FLOATS 39984

__global__ __launch_bounds__(1024, 1) __cluster_dims__(4, 1, 1)
void k_run(const float* __restrict__ bh,  const float* __restrict__ bq,
           const float* __restrict__ uvec,const float* __restrict__ bm,
           const float* __restrict__ Wout,const float* __restrict__ bo,
           float* __restrict__ out)
{
    extern __shared__ __align__(16) float sm[];
    float* s_w    = sm + SM_W;
    float* s_addr = sm + SM_ADDR;
    float* s_cand = sm + SM_CAND;
    float* s_gi   = sm + SM_GI;
    float* s_ghp  = sm + SM_GHP;
    float* s_gmp  = sm + SM_GMP;
    float* s_qp   = sm + SM_QP;
    float* s_cp   = sm + SM_CP;
    float* s_q    = sm + SM_Q;
    float* s_h    = sm + SM_H;
    float* s_r    = sm + SM_R;
    float* s_simp = sm + SM_SIMP;
    float* s_Gp   = sm + SM_GP;
    float* s_rap  = sm + SM_RAP;
    float* s_stat = sm + SM_STAT;
    float* s_bh   = sm + SM_BH;
    float* s_bm   = sm + SM_BM;
    float* s_bq   = sm + SM_BQ;
    float* s_u    = sm + SM_U;
    float* s_Wout = sm + SM_WOUT;
    float* s_bo   = sm + SM_BO;
    float* s_d    = sm + SM_D;
    float* s_G    = sm + SM_G;
    float* s_mx   = sm + SM_MX;
    float* s_e    = sm + SM_E;
    float* s_beta = sm + SM_BETA;

    cg::cluster_group cl = cg::this_cluster();
    const unsigned rank = cl.block_rank();
    float* peer[3];
    #pragma unroll
    for (int i = 0; i < 3; i++)
        peer[i] = (float*)cl.map_shared_rank((void*)sm, (rank + 1 + i) & 3);

    const int b = blockIdx.x >> 2;
    const int r = (int)rank;
    const int tid = threadIdx.x, lane = tid & 31, wl = tid >> 5;
    const float4* h4 = (const float4*)s_h;

    // ---- one-time staging ----
    if (tid < 192) {
        int g = tid >> 6, j = tid & 63;
        s_bh[tid] = bh[g*256 + r*64 + j];
        s_bm[tid] = bm[g*256 + r*64 + j];
    }
    if (tid < 64) s_bq[tid] = bq[r*64 + tid];
    if (tid < 256) { s_u[tid] = uvec[tid]; s_h[tid] = 0.f; }
    for (int i = tid; i < 2560; i += 1024) s_Wout[i] = Wout[i];
    if (tid < 10) s_bo[tid] = bo[tid];
    // addrT quarter -> smem (coalesced)
    for (int i = tid; i < A_*256; i += 1024) {
        int a = i >> 8, nl = i & 255;
        s_addr[i] = g_addrT[a*N_ + r*256 + nl];
    }
    cl.sync();

    for (int t = 0; t < T_; t++) {
        // ===== S1: gh(24w) + q(4w) + cand(4w) partials — r's row quarters =====
        if (wl < 24) {
            int g = wl >> 3, kq = wl & 7;
            int row = g*256 + r*64 + lane*2;
            int k0 = kq << 5;
            float a0 = 0.f, a1 = 0.f;
            #pragma unroll 8
            for (int k = k0; k < k0 + 32; k++) {
                float2 w = *(const float2*)(g_WhT + k*768 + row);
                float hk = s_h[k];
                a0 += w.x*hk; a1 += w.y*hk;
            }
            s_ghp[kq*192 + g*64 + lane*2    ] = a0;
            s_ghp[kq*192 + g*64 + lane*2 + 1] = a1;
        } else if (wl < 28) {
            int kq = wl - 24, k0 = kq << 6;
            int m0 = r*64 + lane*2;
            float a0 = 0.f, a1 = 0.f;
            #pragma unroll 8
            for (int k = k0; k < k0 + 64; k++) {
                float2 w = *(const float2*)(g_WqT + k*256 + m0);
                float hk = s_h[k];
                a0 += w.x*hk; a1 += w.y*hk;
            }
            s_qp[kq*64 + lane*2    ] = a0;
            s_qp[kq*64 + lane*2 + 1] = a1;
        } else {
            int kq = wl - 28, k0 = kq << 6;
            if (lane < 24) {
                int c0 = r*48 + lane*2;
                float a0 = 0.f, a1 = 0.f;
                #pragma unroll 8
                for (int k = k0; k < k0 + 64; k++) {
                    float2 w = *(const float2*)(g_WchT + k*192 + c0);
                    float hk = s_h[k];
                    a0 += w.x*hk; a1 += w.y*hk;
                }
                s_cp[kq*48 + lane*2    ] = a0;
                s_cp[kq*48 + lane*2 + 1] = a1;
            }
        }
        __syncthreads();

        // ===== S2: combines + broadcasts, gi load, beta, head(t-1) =====
        if (tid < 64) {
            float v = s_qp[tid] + s_qp[64 + tid] + s_qp[128 + tid] + s_qp[192 + tid]
                    + s_bq[tid];
            int off = SM_Q + r*64 + tid;
            s_q[r*64 + tid] = v;
            peer[0][off] = v; peer[1][off] = v; peer[2][off] = v;
        } else if (tid < 112) {
            int j = tid - 64;
            float v = s_cp[j] + s_cp[48 + j] + s_cp[96 + j] + s_cp[144 + j]
                    + g_cxA[(t*32 + b)*192 + r*48 + j];
            v = fmaxf(v, 0.f);
            int off = SM_CAND + t*192 + r*48 + j;
            s_cand[t*192 + r*48 + j] = v;
            peer[0][off] = v; peer[1][off] = v; peer[2][off] = v;
        } else if (tid >= 128 && tid < 320) {
            int j = tid - 128;
            int g = j >> 6, jj = j & 63;
            s_gi[j] = g_giA[(t*32 + b)*768 + g*256 + r*64 + jj];
        } else if (wl == 12 && rank == 0) {
            const float4* u4 = (const float4*)s_u;
            float acc = dot8(u4[lane], u4[32 + lane], h4[lane], h4[32 + lane]);
            acc = warp_sum(acc);
            if (lane == 0) {
                float sp = (acc > 0.f) ? acc + log1pf(expf(-acc)) : log1pf(expf(acc));
                float bv = sp + 1.f;
                s_beta[0] = bv;
                peer[0][SM_BETA] = bv; peer[1][SM_BETA] = bv; peer[2][SM_BETA] = bv;
            }
        } else if (wl == 13 && rank == 0 && t > 0) {
            float logit[10];
            float mx = -1e30f;
            #pragma unroll
            for (int o = 0; o < 10; o++) {
                float s = 0.f;
                #pragma unroll
                for (int j = 0; j < 8; j++) {
                    int k = lane + 32*j;
                    s += s_Wout[o*H_ + k] * s_h[k];
                }
                s = warp_sum(s);
                s += s_bo[o];
                logit[o] = s;
                mx = fmaxf(mx, s);
            }
            float se = 0.f;
            #pragma unroll
            for (int o = 0; o < 10; o++) se += expf(logit[o] - mx);
            float lse = mx + logf(se);
            if (lane == 0) {
                #pragma unroll
                for (int o = 0; o < 10; o++)
                    out[HSOFF + ((t-1)*10 + o)*B_ + b] = logit[o] - lse;
            }
        }
        cl.sync();                              // q, cand, beta visible everywhere

        // ===== S3: d_s (replicated, warp per s < t) =====
        if (wl < t) {
            float acc = 0.f;
            #pragma unroll
            for (int j = 0; j < 6; j++) {
                int c = lane + 32*j;
                acc += s_cand[wl*192 + c] * s_q[A_ + c];
            }
            acc = warp_sum(acc);
            if (lane == 0) s_d[wl] = acc;
        }
        __syncthreads();

        // ===== S4: sim partials (all 1024 thr) + cluster softmax =====
        {
            int nl = tid & 255, grp = tid >> 8;
            float acc = 0.f;
            int a0 = grp << 4;
            #pragma unroll
            for (int a = a0; a < a0 + 16; a++)
                acc += s_q[a] * s_addr[a*256 + nl];
            for (int s = grp; s < t; s += 4)
                acc += s_w[s*256 + nl] * s_d[s];
            s_simp[grp*256 + nl] = acc;
        }
        __syncthreads();
        float v = 0.f, e_reg = 0.f, mloc = 0.f;
        if (tid < 256) {
            v = s_beta[0] * (s_simp[tid] + s_simp[256 + tid]
                           + s_simp[512 + tid] + s_simp[768 + tid]);
            float mx = warp_max(v);
            if (lane == 0) s_mx[wl] = mx;
        }
        __syncthreads();
        if (tid < 256) {
            mloc = s_mx[0];
            #pragma unroll
            for (int w = 1; w < 8; w++) mloc = fmaxf(mloc, s_mx[w]);
            e_reg = expf(v - mloc);
            float es = warp_sum(e_reg);
            if (lane == 0) s_e[wl] = es;
        }
        __syncthreads();
        if (tid == 0) {
            float sl = 0.f;
            #pragma unroll
            for (int w = 0; w < 8; w++) sl += s_e[w];
            s_stat[r*2] = mloc; s_stat[r*2 + 1] = sl;
            #pragma unroll
            for (int i = 0; i < 3; i++) {
                peer[i][SM_STAT + r*2] = mloc;
                peer[i][SM_STAT + r*2 + 1] = sl;
            }
        }
        cl.sync();                              // stats visible
        if (tid < 256) {
            float M = fmaxf(fmaxf(s_stat[0], s_stat[2]), fmaxf(s_stat[4], s_stat[6]));
            float S = s_stat[1]*expf(s_stat[0] - M) + s_stat[3]*expf(s_stat[2] - M)
                    + s_stat[5]*expf(s_stat[4] - M) + s_stat[7]*expf(s_stat[6] - M);
            s_w[t*256 + tid] = e_reg * expf(mloc - M) / S;   // local quarter only
        }
        __syncthreads();

        // ===== S5: G partials (warps<t) + ra partials (all warps), smem =====
        if (wl < t) {
            const float4* wsp = (const float4*)(s_w + wl*256);
            const float4* wtp = (const float4*)(s_w + t*256);
            float4 a0 = wsp[lane], c0 = wtp[lane];
            float4 a1 = wsp[32 + lane], c1 = wtp[32 + lane];
            float g = a0.x*c0.x + a0.y*c0.y + a0.z*c0.z + a0.w*c0.w
                    + a1.x*c1.x + a1.y*c1.y + a1.z*c1.z + a1.w*c1.w;
            g = warp_sum(g);
            if (lane == 0) {
                int off = SM_GP + r*32 + wl;
                s_Gp[r*32 + wl] = g;
                peer[0][off] = g; peer[1][off] = g; peer[2][off] = g;
            }
        }
        {
            const float4* wtp = (const float4*)(s_w + t*256);
            const float4* at0 = (const float4*)(s_addr + wl*256);
            const float4* at1 = (const float4*)(s_addr + (wl + 32)*256);
            float4 w0 = wtp[lane], w1 = wtp[32 + lane];
            float4 x0 = at0[lane], x1 = at0[32 + lane];
            float4 y0 = at1[lane], y1 = at1[32 + lane];
            float a0 = w0.x*x0.x + w0.y*x0.y + w0.z*x0.z + w0.w*x0.w
                     + w1.x*x1.x + w1.y*x1.y + w1.z*x1.z + w1.w*x1.w;
            float a1 = w0.x*y0.x + w0.y*y0.y + w0.z*y0.z + w0.w*y0.w
                     + w1.x*y1.x + w1.y*y1.y + w1.z*y1.z + w1.w*y1.w;
            a0 = warp_sum(a0);
            a1 = warp_sum(a1);
            if (lane == 0) {
                int off0 = SM_RAP + r*64 + wl;
                int off1 = SM_RAP + r*64 + wl + 32;
                s_rap[r*64 + wl] = a0;
                s_rap[r*64 + wl + 32] = a1;
                peer[0][off0] = a0; peer[1][off0] = a0; peer[2][off0] = a0;
                peer[0][off1] = a1; peer[1][off1] = a1; peer[2][off1] = a1;
            }
        }
        cl.sync();                              // G/ra partials visible

        // ===== S6: combine G + ra, then rc =====
        if (tid < 32) {
            s_G[tid] = s_Gp[tid] + s_Gp[32 + tid] + s_Gp[64 + tid] + s_Gp[96 + tid];
        } else if (tid < 96) {
            int a = tid - 32;
            s_r[a] = s_rap[a] + s_rap[64 + a] + s_rap[128 + a] + s_rap[192 + a];
        }
        __syncthreads();
        if (tid < 192) {
            float acc = 0.f;
            for (int s = 0; s < t; s++)
                acc += s_G[s] * s_cand[s*192 + tid];
            s_r[A_ + tid] = acc;
        }
        __syncthreads();

        // ===== S7: gm partials (24 warps, r's row quarter) =====
        if (wl < 24) {
            int g = wl >> 3, kq = wl & 7;
            int row = g*256 + r*64 + lane*2;
            int m0 = kq << 5;
            float a0 = 0.f, a1 = 0.f;
            #pragma unroll 8
            for (int m = m0; m < m0 + 32; m++) {
                float2 w = *(const float2*)(g_WmT + m*768 + row);
                float rm = s_r[m];
                a0 += w.x*rm; a1 += w.y*rm;
            }
            s_gmp[kq*192 + g*64 + lane*2    ] = a0;
            s_gmp[kq*192 + g*64 + lane*2 + 1] = a1;
        }
        __syncthreads();

        // ===== S8: gate combine + h slice update + broadcast =====
        if (tid < 64) {
            int hid = r*64 + tid;
            float gh0 = s_bh[tid],       gm0 = s_bm[tid];
            float gh1 = s_bh[64 + tid],  gm1 = s_bm[64 + tid];
            float gh2 = s_bh[128 + tid], gm2 = s_bm[128 + tid];
            #pragma unroll
            for (int kq = 0; kq < 8; kq++) {
                gh0 += s_ghp[kq*192 + tid];
                gh1 += s_ghp[kq*192 + 64 + tid];
                gh2 += s_ghp[kq*192 + 128 + tid];
                gm0 += s_gmp[kq*192 + tid];
                gm1 += s_gmp[kq*192 + 64 + tid];
                gm2 += s_gmp[kq*192 + 128 + tid];
            }
            float rr = 1.f / (1.f + expf(-(s_gi[tid] + gh0 + gm0)));
            float zz = 1.f / (1.f + expf(-(s_gi[64 + tid] + gh1 + gm1)));
            float nn = tanhf(s_gi[128 + tid] + gm2 + rr*gh2);
            float hn = (1.f - zz)*nn + zz*s_h[hid];
            int off = SM_H + hid;
            s_h[hid] = hn;
            peer[0][off] = hn; peer[1][off] = hn; peer[2][off] = hn;
            out[t*H_*B_ + hid*32 + b] = hn;
        }
        cl.sync();                              // full h visible
    }

    // final head (t = T-1), rank 0
    if (rank == 0 && wl == 0) {
        float logit[10];
        float mx = -1e30f;
        #pragma unroll
        for (int o = 0; o < 10; o++) {
            float s = 0.f;
            #pragma unroll
            for (int j = 0; j < 8; j++) {
                int k = lane + 32*j;
                s += s_Wout[o*H_ + k] * s_h[k];
            }
            s = warp_sum(s);
            s += s_bo[o];
            logit[o] = s;
            mx = fmaxf(mx, s);
        }
        float se = 0.f;
        #pragma unroll
        for (int o = 0; o < 10; o++) se += expf(logit[o] - mx);
        float lse = mx + logf(se);
        if (lane == 0) {
            #pragma unroll
            for (int o = 0; o < 10; o++)
                out[HSOFF + ((T_-1)*10 + o)*B_ + b] = logit[o] - lse;
        }
    }
}

extern "C" void kernel_launch(void* const* d_in, const int* in_sizes, int n_in,
                              void* d_out, int out_size) {
    (void)in_sizes; (void)n_in; (void)out_size;
    const float* batch = (const float*)d_in[0];
    const float* Wi    = (const float*)d_in[1];
    const float* bi    = (const float*)d_in[2];
    const float* Wh    = (const float*)d_in[3];
    const float* bh    = (const float*)d_in[4];
    const float* Wm    = (const float*)d_in[5];
    const float* bm    = (const float*)d_in[6];
    const float* Wout  = (const float*)d_in[7];
    const float* bo    = (const float*)d_in[8];
    const float* addr  = (const float*)d_in[9];
    const float* Wq    = (const float*)d_in[10];
    const float* bq    = (const float*)d_in[11];
    const float* u     = (const float*)d_in[12];
    const float* Wch   = (const float*)d_in[13];
    const float* Wci   = (const float*)d_in[14];
    float* out = (float*)d_out;

    static int smem_set = 0;
    if (!smem_set) {
        cudaFuncSetAttribute((const void*)k_run,
                             cudaFuncAttributeMaxDynamicSharedMemorySize,
                             SMEM_FLOATS * 4);
        smem_set = 1;
    }
    k_tr<<<560, 256>>>(Wh, Wq, Wch, Wm, addr);
    k_init<<<1024, 256>>>(batch, Wi, bi, Wci);
    k_run<<<128, 1024, SMEM_FLOATS * 4>>>(bh, bq, u, bm, Wout, bo, out);
}